// round 1
// baseline (speedup 1.0000x reference)
#include <cuda_runtime.h>

#define S_LEN 4096
#define EMB   1024
#define HEAD  64
#define BATCH 4
#define M_TOTAL (BATCH * S_LEN)   // 16384

// Scratch for Q, K, V projections: 3 x 16384 x 64 floats = 12 MB
__device__ float g_QKV[3][M_TOTAL * HEAD];

// ---------------------------------------------------------------------------
// Kernel 1: QKV projection.  C[m][n] = sum_k x[m][k] * W[k][n] + b[n]
// Tiling: BM=64, BN=64, BK=16. 256 threads (16x16), 4x4 micro-tile each.
// A (x) stored k-major in smem with XOR chunk swizzle; B (W) natural.
// grid = (256, 3)  [3 selects Wq/Wk/Wv]
// ---------------------------------------------------------------------------
__global__ __launch_bounds__(256) void qkv_kernel(
    const float* __restrict__ x,
    const float* __restrict__ Wq, const float* __restrict__ bq,
    const float* __restrict__ Wk, const float* __restrict__ bk,
    const float* __restrict__ Wv, const float* __restrict__ bv)
{
    __shared__ float As[16 * 64];   // [kk][m] swizzled
    __shared__ float Bs[16 * 64];   // [kk][n] natural

    const int which = blockIdx.y;
    const float* W    = (which == 0) ? Wq : (which == 1) ? Wk : Wv;
    const float* bias = (which == 0) ? bq : (which == 1) ? bk : bv;
    float* out = g_QKV[which];

    const int t  = threadIdx.x;
    const int tx = t & 15;
    const int ty = t >> 4;
    const int row0 = blockIdx.x * 64;

    // A-load mapping: thread covers row m = t>>2, k-quad kq = t&3
    const int am  = t >> 2;
    const int akq = t & 3;
    const int amh = am >> 2;   // chunk of m
    const int aml = am & 3;
    // B-load mapping
    const int bkk = t >> 4;
    const int bc  = t & 15;

    float acc[4][4] = {};

    for (int k0 = 0; k0 < EMB; k0 += 16) {
        __syncthreads();
        // ---- load x tile [64 rows x 16 k] transposed + swizzled ----
        float4 av = *(const float4*)&x[(row0 + am) * EMB + k0 + akq * 4];
        {
            const float* avp = (const float*)&av;
            #pragma unroll
            for (int u = 0; u < 4; u++) {
                int r = akq * 4 + u;                       // local k
                As[r * 64 + 4 * (amh ^ r) + aml] = avp[u];
            }
        }
        // ---- load W tile [16 k x 64 n] natural ----
        *(float4*)&Bs[bkk * 64 + bc * 4] =
            *(const float4*)&W[(k0 + bkk) * HEAD + bc * 4];
        __syncthreads();

        #pragma unroll
        for (int kk = 0; kk < 16; kk++) {
            float4 a4 = *(const float4*)&As[kk * 64 + 4 * (ty ^ kk)];
            float4 b4 = *(const float4*)&Bs[kk * 64 + 4 * tx];
            float a[4] = {a4.x, a4.y, a4.z, a4.w};
            float b[4] = {b4.x, b4.y, b4.z, b4.w};
            #pragma unroll
            for (int i = 0; i < 4; i++)
                #pragma unroll
                for (int j = 0; j < 4; j++)
                    acc[i][j] += a[i] * b[j];
        }
    }

    float4 bb = *(const float4*)&bias[tx * 4];
    #pragma unroll
    for (int i = 0; i < 4; i++) {
        float4 o;
        o.x = acc[i][0] + bb.x;
        o.y = acc[i][1] + bb.y;
        o.z = acc[i][2] + bb.z;
        o.w = acc[i][3] + bb.w;
        *(float4*)&out[(row0 + 4 * ty + i) * HEAD + 4 * tx] = o;
    }
}

// ---------------------------------------------------------------------------
// Kernel 2: causal flash attention. BQ = BK = 64, HEAD = 64.
// 256 threads (16x16), each owns 4 query rows x 4 cols.
// smem: Qt (d-major, swizzled, pre-scaled), KP = Kt aliased with Pt, Vs natural.
// grid = (64, 4)  [x: query block (reversed for balance), y: batch]
// ---------------------------------------------------------------------------
__global__ __launch_bounds__(256) void attn_kernel(float* __restrict__ out)
{
    __shared__ float Qt[64 * 64];   // [d][q] swizzled
    __shared__ float KP[64 * 64];   // Kt [d][k] swizzled  /  Pt [k][q] swizzled
    __shared__ float Vs[64 * 64];   // [k][d] natural

    const float* Q = g_QKV[0];
    const float* K = g_QKV[1];
    const float* V = g_QKV[2];

    const int b  = blockIdx.y;
    const int qb = (gridDim.x - 1) - blockIdx.x;   // heavy blocks first
    const int t  = threadIdx.x;
    const int tx = t & 15;
    const int ty = t >> 4;
    const int base = b * S_LEN * HEAD;

    // ---- load Q tile: transpose + swizzle + pre-scale by 1/sqrt(64) ----
    {
        const int q  = t >> 2;       // row in tile
        const int qh = q >> 2, ql = q & 3;
        #pragma unroll
        for (int r = 0; r < 4; r++) {
            int dq = 4 * (t & 3) + r;   // float4 index along d
            float4 v = *(const float4*)&Q[base + (qb * 64 + q) * HEAD + dq * 4];
            const float* vp = (const float*)&v;
            #pragma unroll
            for (int u = 0; u < 4; u++) {
                int d = dq * 4 + u;
                Qt[d * 64 + 4 * (qh ^ (d & 15)) + ql] = vp[u] * 0.125f;
            }
        }
    }

    float o[4][4] = {};
    float m_i[4], l_i[4];
    #pragma unroll
    for (int i = 0; i < 4; i++) { m_i[i] = -1e30f; l_i[i] = 0.0f; }

    for (int kb = 0; kb <= qb; kb++) {
        __syncthreads();   // prev iter done reading KP(Pt) / Vs

        // ---- load K tile transposed + swizzled into KP ----
        {
            const int k  = t >> 2;
            const int kh = k >> 2, kl = k & 3;
            #pragma unroll
            for (int r = 0; r < 4; r++) {
                int dq = 4 * (t & 3) + r;
                float4 v = *(const float4*)&K[base + (kb * 64 + k) * HEAD + dq * 4];
                const float* vp = (const float*)&v;
                #pragma unroll
                for (int u = 0; u < 4; u++) {
                    int d = dq * 4 + u;
                    KP[d * 64 + 4 * (kh ^ (d & 15)) + kl] = vp[u];
                }
            }
        }
        // ---- load V tile natural ----
        #pragma unroll
        for (int r = 0; r < 4; r++) {
            int lin = 256 * r + t;
            int k2 = lin >> 4, dc = lin & 15;
            *(float4*)&Vs[k2 * 64 + dc * 4] =
                *(const float4*)&V[base + (kb * 64 + k2) * HEAD + dc * 4];
        }
        __syncthreads();

        // ---- scores: s[i][j] = sum_d Qt[d][4ty+i] * Kt[d][4tx+j] ----
        float s[4][4] = {};
        #pragma unroll 8
        for (int d = 0; d < 64; d++) {
            float4 a4 = *(const float4*)&Qt[d * 64 + 4 * (ty ^ (d & 15))];
            float4 b4 = *(const float4*)&KP[d * 64 + 4 * (tx ^ (d & 15))];
            float a[4] = {a4.x, a4.y, a4.z, a4.w};
            float bv[4] = {b4.x, b4.y, b4.z, b4.w};
            #pragma unroll
            for (int i = 0; i < 4; i++)
                #pragma unroll
                for (int j = 0; j < 4; j++)
                    s[i][j] += a[i] * bv[j];
        }

        // ---- causal mask on diagonal block ----
        if (kb == qb) {
            #pragma unroll
            for (int i = 0; i < 4; i++)
                #pragma unroll
                for (int j = 0; j < 4; j++)
                    if (4 * tx + j > 4 * ty + i) s[i][j] = -1e30f;
        }

        // ---- online softmax (row = query, spread over 16 tx lanes) ----
        #pragma unroll
        for (int i = 0; i < 4; i++) {
            float mx = fmaxf(fmaxf(s[i][0], s[i][1]), fmaxf(s[i][2], s[i][3]));
            #pragma unroll
            for (int off = 1; off < 16; off <<= 1)
                mx = fmaxf(mx, __shfl_xor_sync(0xffffffffu, mx, off, 16));
            float mnew = fmaxf(m_i[i], mx);
            float alpha = __expf(m_i[i] - mnew);
            m_i[i] = mnew;
            float rs = 0.0f;
            #pragma unroll
            for (int j = 0; j < 4; j++) {
                s[i][j] = __expf(s[i][j] - mnew);
                rs += s[i][j];
            }
            #pragma unroll
            for (int off = 1; off < 16; off <<= 1)
                rs += __shfl_xor_sync(0xffffffffu, rs, off, 16);
            l_i[i] = l_i[i] * alpha + rs;
            #pragma unroll
            for (int j = 0; j < 4; j++) o[i][j] *= alpha;
        }

        __syncthreads();   // everyone done reading Kt before overwrite as Pt

        // ---- write P^T into KP: Pt[k][q] swizzled ----
        #pragma unroll
        for (int j = 0; j < 4; j++) {
            int k = 4 * tx + j;
            float4 p4 = make_float4(s[0][j], s[1][j], s[2][j], s[3][j]);
            *(float4*)&KP[k * 64 + 4 * (ty ^ (k & 15))] = p4;
        }
        __syncthreads();

        // ---- O += P * V ----
        #pragma unroll 8
        for (int k = 0; k < 64; k++) {
            float4 a4 = *(const float4*)&KP[k * 64 + 4 * (ty ^ (k & 15))];
            float4 b4 = *(const float4*)&Vs[k * 64 + 4 * tx];
            float a[4] = {a4.x, a4.y, a4.z, a4.w};
            float bv[4] = {b4.x, b4.y, b4.z, b4.w};
            #pragma unroll
            for (int i = 0; i < 4; i++)
                #pragma unroll
                for (int j = 0; j < 4; j++)
                    o[i][j] += a[i] * bv[j];
        }
    }

    // ---- epilogue: normalize and store ----
    #pragma unroll
    for (int i = 0; i < 4; i++) {
        float inv = 1.0f / l_i[i];
        float4 ov = make_float4(o[i][0] * inv, o[i][1] * inv,
                                o[i][2] * inv, o[i][3] * inv);
        *(float4*)&out[base + (qb * 64 + 4 * ty + i) * HEAD + 4 * tx] = ov;
    }
}

// ---------------------------------------------------------------------------
extern "C" void kernel_launch(void* const* d_in, const int* in_sizes, int n_in,
                              void* d_out, int out_size)
{
    const float* x  = (const float*)d_in[0];
    const float* Wq = (const float*)d_in[1];
    const float* bq = (const float*)d_in[2];
    const float* Wk = (const float*)d_in[3];
    const float* bk = (const float*)d_in[4];
    const float* Wv = (const float*)d_in[5];
    const float* bv = (const float*)d_in[6];
    float* out = (float*)d_out;

    dim3 g1(M_TOTAL / 64, 3);
    qkv_kernel<<<g1, 256>>>(x, Wq, bq, Wk, bk, Wv, bv);

    dim3 g2(S_LEN / 64, BATCH);
    attn_kernel<<<g2, 256>>>(out);
}

// round 3
// speedup vs baseline: 2.3084x; 2.3084x over previous
#include <cuda_runtime.h>
#include <cstdint>

#define S_LEN 4096
#define EMB   1024
#define HEAD  64
#define BATCH 4
#define M_TOTAL (BATCH * S_LEN)   // 16384

// Scratch for Q, K, V projections
__device__ float g_QKV[3][M_TOTAL * HEAD];

// ---------------------------------------------------------------------------
// tf32 helpers
// ---------------------------------------------------------------------------
__device__ __forceinline__ uint32_t f2tf(float f) {
    uint32_t r;
    asm("cvt.rna.tf32.f32 %0, %1;" : "=r"(r) : "f"(f));
    return r;
}

__device__ __forceinline__ void mma_tf32(float c[4],
                                         const uint32_t a[4],
                                         const uint32_t b[2]) {
    asm volatile(
        "mma.sync.aligned.m16n8k8.row.col.f32.tf32.tf32.f32 "
        "{%0,%1,%2,%3}, {%4,%5,%6,%7}, {%8,%9}, {%0,%1,%2,%3};\n"
        : "+f"(c[0]), "+f"(c[1]), "+f"(c[2]), "+f"(c[3])
        : "r"(a[0]), "r"(a[1]), "r"(a[2]), "r"(a[3]),
          "r"(b[0]), "r"(b[1]));
}

// ---------------------------------------------------------------------------
// Kernel 1: QKV projection via tf32 MMA.
// C[16384,64] = x[16384,1024] @ W[1024,64] + b
// Block: BM=128, BN=64, BK=32, 256 threads (8 warps as 4x2, warp tile 32x32)
// As: [k][m] stride 132 (conflict-free A-frag reads: (4c+r) bijection)
// Bs: [k][n] stride 72  (conflict-free B-frag reads: (8k+n) bijection)
// ---------------------------------------------------------------------------
__global__ __launch_bounds__(256) void qkv_kernel(
    const float* __restrict__ x,
    const float* __restrict__ Wq, const float* __restrict__ bq,
    const float* __restrict__ Wk, const float* __restrict__ bk,
    const float* __restrict__ Wv, const float* __restrict__ bv)
{
    __shared__ float As[32 * 132];
    __shared__ float Bs[32 * 72];

    const int which = blockIdx.y;
    const float* W    = (which == 0) ? Wq : (which == 1) ? Wk : Wv;
    const float* bias = (which == 0) ? bq : (which == 1) ? bk : bv;
    float* out = g_QKV[which];

    const int t    = threadIdx.x;
    const int lane = t & 31;
    const int warp = t >> 5;
    const int wy   = warp >> 1;          // 0..3 (m)
    const int wx   = warp & 1;           // 0..1 (n)
    const int m0   = wy * 32;
    const int n0   = wx * 32;
    const int row0 = blockIdx.x * 128;

    const int r = lane >> 2;             // groupID
    const int c = lane & 3;              // threadID in group

    float acc[2][4][4] = {};

    for (int k0 = 0; k0 < EMB; k0 += 32) {
        __syncthreads();
        // ---- x tile -> As[k][m] (transpose + cvt) ----
        #pragma unroll
        for (int i = 0; i < 4; i++) {
            int idx = t + 256 * i;             // 1024 float4s
            int m  = idx >> 3;
            int kq = idx & 7;
            float4 v = *(const float4*)&x[(row0 + m) * EMB + k0 + 4 * kq];
            As[(4 * kq + 0) * 132 + m] = __uint_as_float(f2tf(v.x));
            As[(4 * kq + 1) * 132 + m] = __uint_as_float(f2tf(v.y));
            As[(4 * kq + 2) * 132 + m] = __uint_as_float(f2tf(v.z));
            As[(4 * kq + 3) * 132 + m] = __uint_as_float(f2tf(v.w));
        }
        // ---- W tile -> Bs[k][n] ----
        #pragma unroll
        for (int i = 0; i < 2; i++) {
            int idx = t + 256 * i;             // 512 float4s
            int k  = idx >> 4;
            int nq = idx & 15;
            float4 v = *(const float4*)&W[(k0 + k) * HEAD + 4 * nq];
            uint4 u;
            u.x = f2tf(v.x); u.y = f2tf(v.y); u.z = f2tf(v.z); u.w = f2tf(v.w);
            *(uint4*)&Bs[k * 72 + 4 * nq] = u;
        }
        __syncthreads();

        #pragma unroll
        for (int ks = 0; ks < 4; ks++) {
            uint32_t afrag[2][4];
            #pragma unroll
            for (int mt = 0; mt < 2; mt++) {
                int mm = m0 + mt * 16 + r;
                afrag[mt][0] = __float_as_uint(As[(ks * 8 + c)     * 132 + mm]);
                afrag[mt][1] = __float_as_uint(As[(ks * 8 + c)     * 132 + mm + 8]);
                afrag[mt][2] = __float_as_uint(As[(ks * 8 + c + 4) * 132 + mm]);
                afrag[mt][3] = __float_as_uint(As[(ks * 8 + c + 4) * 132 + mm + 8]);
            }
            #pragma unroll
            for (int nt = 0; nt < 4; nt++) {
                uint32_t bfrag[2];
                int nn = n0 + nt * 8 + r;
                bfrag[0] = __float_as_uint(Bs[(ks * 8 + c)     * 72 + nn]);
                bfrag[1] = __float_as_uint(Bs[(ks * 8 + c + 4) * 72 + nn]);
                mma_tf32(acc[0][nt], afrag[0], bfrag);
                mma_tf32(acc[1][nt], afrag[1], bfrag);
            }
        }
    }

    // ---- epilogue: +bias, store float2 pairs ----
    #pragma unroll
    for (int mt = 0; mt < 2; mt++) {
        #pragma unroll
        for (int nt = 0; nt < 4; nt++) {
            int n = n0 + nt * 8 + 2 * c;
            float b0 = bias[n], b1 = bias[n + 1];
            int mA = row0 + m0 + mt * 16 + r;
            *(float2*)&out[mA * HEAD + n] =
                make_float2(acc[mt][nt][0] + b0, acc[mt][nt][1] + b1);
            *(float2*)&out[(mA + 8) * HEAD + n] =
                make_float2(acc[mt][nt][2] + b0, acc[mt][nt][3] + b1);
        }
    }
}

// ---------------------------------------------------------------------------
// Kernel 2: causal flash attention via tf32 MMA.
// BQ=64, BK=64, D=64. 128 threads (4 warps), warp owns 16 q-rows.
// Q kept entirely in registers as A-fragments (pre-scaled by 1/8).
// Ks: [d][key] stride 72 (B-frags for QK^T), aliased with per-warp P slabs.
// Vs: [key][d] stride 72 (B-frags for PV).
// Ps: per-warp [16][68] (conflict-free A-frag reads: (4r+c) bijection)
// ---------------------------------------------------------------------------
__global__ __launch_bounds__(128) void attn_kernel(float* __restrict__ out)
{
    __shared__ float Ks[64 * 72];   // 18.4 KB, aliased with P slabs
    __shared__ float Vs[64 * 72];   // 18.4 KB

    const float* Q = g_QKV[0];
    const float* K = g_QKV[1];
    const float* V = g_QKV[2];

    const int b    = blockIdx.y;
    const int qb   = (gridDim.x - 1) - blockIdx.x;   // heavy blocks first
    const int t    = threadIdx.x;
    const int lane = t & 31;
    const int warp = t >> 5;
    const int base = b * S_LEN * HEAD;

    const int r = lane >> 2;      // groupID (row in fragment)
    const int c = lane & 3;       // threadID in group

    float* Psw = Ks + warp * (16 * 68);   // this warp's P slab

    // ---- load Q fragments into registers (scaled, tf32) ----
    uint32_t qa[8][4];
    {
        const int qrow = qb * 64 + warp * 16 + r;
        #pragma unroll
        for (int kt = 0; kt < 8; kt++) {
            int d = kt * 8 + c;
            qa[kt][0] = f2tf(Q[base + qrow * HEAD + d] * 0.125f);
            qa[kt][1] = f2tf(Q[base + (qrow + 8) * HEAD + d] * 0.125f);
            qa[kt][2] = f2tf(Q[base + qrow * HEAD + d + 4] * 0.125f);
            qa[kt][3] = f2tf(Q[base + (qrow + 8) * HEAD + d + 4] * 0.125f);
        }
    }

    float oacc[8][4] = {};
    float mA = -1e30f, mB = -1e30f, lA = 0.0f, lB = 0.0f;

    for (int kb = 0; kb <= qb; kb++) {
        __syncthreads();   // prev iter done with Ps(=Ks) and Vs

        // ---- load K tile -> Ks[d][key], V tile -> Vs[key][d], both tf32 ----
        #pragma unroll
        for (int i = 0; i < 8; i++) {
            int idx = t + 128 * i;            // 1024 float4s
            int key = idx >> 4;
            int dq  = idx & 15;
            int grow = base + (kb * 64 + key) * HEAD + 4 * dq;
            float4 kv = *(const float4*)&K[grow];
            Ks[(4 * dq + 0) * 72 + key] = __uint_as_float(f2tf(kv.x));
            Ks[(4 * dq + 1) * 72 + key] = __uint_as_float(f2tf(kv.y));
            Ks[(4 * dq + 2) * 72 + key] = __uint_as_float(f2tf(kv.z));
            Ks[(4 * dq + 3) * 72 + key] = __uint_as_float(f2tf(kv.w));
            float4 vv = *(const float4*)&V[grow];
            uint4 u;
            u.x = f2tf(vv.x); u.y = f2tf(vv.y); u.z = f2tf(vv.z); u.w = f2tf(vv.w);
            *(uint4*)&Vs[key * 72 + 4 * dq] = u;
        }
        __syncthreads();

        // ---- S = Q K^T : 8 n-tiles of m16n8, K as B-frags ----
        float sacc[8][4] = {};
        #pragma unroll
        for (int dk = 0; dk < 8; dk++) {
            #pragma unroll
            for (int nt = 0; nt < 8; nt++) {
                uint32_t bfrag[2];
                int key = nt * 8 + r;
                bfrag[0] = __float_as_uint(Ks[(dk * 8 + c)     * 72 + key]);
                bfrag[1] = __float_as_uint(Ks[(dk * 8 + c + 4) * 72 + key]);
                mma_tf32(sacc[nt], qa[dk], bfrag);
            }
        }

        // ---- causal mask on diagonal block ----
        if (kb == qb) {
            int qA = warp * 16 + r;     // local
            int qB = qA + 8;
            #pragma unroll
            for (int nt = 0; nt < 8; nt++) {
                int k0l = nt * 8 + 2 * c;
                if (k0l     > qA) sacc[nt][0] = -1e30f;
                if (k0l + 1 > qA) sacc[nt][1] = -1e30f;
                if (k0l     > qB) sacc[nt][2] = -1e30f;
                if (k0l + 1 > qB) sacc[nt][3] = -1e30f;
            }
        }

        // ---- online softmax (rows rA = r, rB = r+8; 4 lanes share a row) ----
        {
            float mxA = -1e30f, mxB = -1e30f;
            #pragma unroll
            for (int nt = 0; nt < 8; nt++) {
                mxA = fmaxf(mxA, fmaxf(sacc[nt][0], sacc[nt][1]));
                mxB = fmaxf(mxB, fmaxf(sacc[nt][2], sacc[nt][3]));
            }
            mxA = fmaxf(mxA, __shfl_xor_sync(0xffffffffu, mxA, 1, 4));
            mxA = fmaxf(mxA, __shfl_xor_sync(0xffffffffu, mxA, 2, 4));
            mxB = fmaxf(mxB, __shfl_xor_sync(0xffffffffu, mxB, 1, 4));
            mxB = fmaxf(mxB, __shfl_xor_sync(0xffffffffu, mxB, 2, 4));
            float mnA = fmaxf(mA, mxA);
            float mnB = fmaxf(mB, mxB);
            float alA = __expf(mA - mnA);
            float alB = __expf(mB - mnB);
            mA = mnA; mB = mnB;
            float rsA = 0.0f, rsB = 0.0f;
            #pragma unroll
            for (int nt = 0; nt < 8; nt++) {
                sacc[nt][0] = __expf(sacc[nt][0] - mnA);
                sacc[nt][1] = __expf(sacc[nt][1] - mnA);
                sacc[nt][2] = __expf(sacc[nt][2] - mnB);
                sacc[nt][3] = __expf(sacc[nt][3] - mnB);
                rsA += sacc[nt][0] + sacc[nt][1];
                rsB += sacc[nt][2] + sacc[nt][3];
            }
            rsA += __shfl_xor_sync(0xffffffffu, rsA, 1, 4);
            rsA += __shfl_xor_sync(0xffffffffu, rsA, 2, 4);
            rsB += __shfl_xor_sync(0xffffffffu, rsB, 1, 4);
            rsB += __shfl_xor_sync(0xffffffffu, rsB, 2, 4);
            lA = lA * alA + rsA;
            lB = lB * alB + rsB;
            #pragma unroll
            for (int dt = 0; dt < 8; dt++) {
                oacc[dt][0] *= alA; oacc[dt][1] *= alA;
                oacc[dt][2] *= alB; oacc[dt][3] *= alB;
            }
        }

        __syncthreads();   // all warps done reading Ks before P overwrite

        // ---- write P^T... P into own slab as tf32 (C-layout -> smem) ----
        #pragma unroll
        for (int nt = 0; nt < 8; nt++) {
            int col = nt * 8 + 2 * c;
            uint2 p0, p1;
            p0.x = f2tf(sacc[nt][0]); p0.y = f2tf(sacc[nt][1]);
            p1.x = f2tf(sacc[nt][2]); p1.y = f2tf(sacc[nt][3]);
            *(uint2*)&Psw[r * 68 + col]       = p0;
            *(uint2*)&Psw[(r + 8) * 68 + col] = p1;
        }
        __syncwarp();

        // ---- O += P V : P as A-frags from own slab, V as B-frags ----
        #pragma unroll
        for (int kt = 0; kt < 8; kt++) {
            uint32_t pa[4];
            pa[0] = __float_as_uint(Psw[r * 68 + kt * 8 + c]);
            pa[1] = __float_as_uint(Psw[(r + 8) * 68 + kt * 8 + c]);
            pa[2] = __float_as_uint(Psw[r * 68 + kt * 8 + c + 4]);
            pa[3] = __float_as_uint(Psw[(r + 8) * 68 + kt * 8 + c + 4]);
            #pragma unroll
            for (int dt = 0; dt < 8; dt++) {
                uint32_t vb[2];
                int dcol = dt * 8 + r;
                vb[0] = __float_as_uint(Vs[(kt * 8 + c)     * 72 + dcol]);
                vb[1] = __float_as_uint(Vs[(kt * 8 + c + 4) * 72 + dcol]);
                mma_tf32(oacc[dt], pa, vb);
            }
        }
    }

    // ---- epilogue ----
    {
        float invA = 1.0f / lA;
        float invB = 1.0f / lB;
        int qrow = qb * 64 + warp * 16 + r;
        #pragma unroll
        for (int dt = 0; dt < 8; dt++) {
            int d = dt * 8 + 2 * c;
            *(float2*)&out[base + qrow * HEAD + d] =
                make_float2(oacc[dt][0] * invA, oacc[dt][1] * invA);
            *(float2*)&out[base + (qrow + 8) * HEAD + d] =
                make_float2(oacc[dt][2] * invB, oacc[dt][3] * invB);
        }
    }
}

// ---------------------------------------------------------------------------
extern "C" void kernel_launch(void* const* d_in, const int* in_sizes, int n_in,
                              void* d_out, int out_size)
{
    const float* x  = (const float*)d_in[0];
    const float* Wq = (const float*)d_in[1];
    const float* bq = (const float*)d_in[2];
    const float* Wk = (const float*)d_in[3];
    const float* bk = (const float*)d_in[4];
    const float* Wv = (const float*)d_in[5];
    const float* bv = (const float*)d_in[6];
    float* out = (float*)d_out;

    dim3 g1(M_TOTAL / 128, 3);
    qkv_kernel<<<g1, 256>>>(x, Wq, bq, Wk, bk, Wv, bv);

    dim3 g2(S_LEN / 64, BATCH);
    attn_kernel<<<g2, 128>>>(out);
}

// round 5
// speedup vs baseline: 3.6659x; 1.5881x over previous
#include <cuda_runtime.h>
#include <cstdint>

#define S_LEN 4096
#define EMB   1024
#define HEAD  64
#define BATCH 4
#define M_TOTAL (BATCH * S_LEN)   // 16384

__device__ float g_QKV[3][M_TOTAL * HEAD];

// ---------------------------------------------------------------------------
// helpers
// ---------------------------------------------------------------------------
__device__ __forceinline__ uint32_t f2tf(float f) {
    uint32_t r;
    asm("cvt.rna.tf32.f32 %0, %1;" : "=r"(r) : "f"(f));
    return r;
}

__device__ __forceinline__ void mma_tf32(float c[4],
                                         const uint32_t a[4],
                                         const uint32_t b[2]) {
    asm volatile(
        "mma.sync.aligned.m16n8k8.row.col.f32.tf32.tf32.f32 "
        "{%0,%1,%2,%3}, {%4,%5,%6,%7}, {%8,%9}, {%0,%1,%2,%3};\n"
        : "+f"(c[0]), "+f"(c[1]), "+f"(c[2]), "+f"(c[3])
        : "r"(a[0]), "r"(a[1]), "r"(a[2]), "r"(a[3]),
          "r"(b[0]), "r"(b[1]));
}

__device__ __forceinline__ void cp16(float* s, const float* g) {
    uint32_t sa = (uint32_t)__cvta_generic_to_shared(s);
    asm volatile("cp.async.cg.shared.global [%0], [%1], 16;\n"
                 :: "r"(sa), "l"(g));
}
#define CP_COMMIT() asm volatile("cp.async.commit_group;\n")
#define CP_WAIT0()  asm volatile("cp.async.wait_group 0;\n")

// ---------------------------------------------------------------------------
// Kernel 1: QKV projection.  BM=128, BN=64, BK=32, 256 thr (8 warps 4x2).
// As: raw fp32, natural [m][k], stride 36; Bs: raw fp32, [k][n], stride 72.
// RNA tf32 conversion happens in-register at fragment build (kills the
// biased-truncation error accumulation over K=1024).
// K/V outputs are written ALREADY RNA-ROUNDED to tf32 so the attention
// kernel can consume them raw (HW truncation then lossless).
// ---------------------------------------------------------------------------
#define QKV_AS(buf)  (sm + (buf) * 4608)          // 128*36
#define QKV_BS(buf)  (sm + 9216 + (buf) * 2304)   // 32*72
#define QKV_SMEM_BYTES 55296

__global__ __launch_bounds__(256) void qkv_kernel(
    const float* __restrict__ x,
    const float* __restrict__ Wq, const float* __restrict__ bq,
    const float* __restrict__ Wk, const float* __restrict__ bk,
    const float* __restrict__ Wv, const float* __restrict__ bv)
{
    extern __shared__ float sm[];

    const int which = blockIdx.y;
    const float* W    = (which == 0) ? Wq : (which == 1) ? Wk : Wv;
    const float* bias = (which == 0) ? bq : (which == 1) ? bk : bv;
    float* out = g_QKV[which];

    const int t    = threadIdx.x;
    const int lane = t & 31;
    const int warp = t >> 5;
    const int m0   = (warp >> 1) * 32;
    const int n0   = (warp & 1) * 32;
    const int row0 = blockIdx.x * 128;

    const int r = lane >> 2;
    const int c = lane & 3;

    auto prefetch = [&](int k0, int buf) {
        float* Ab = QKV_AS(buf);
        float* Bb = QKV_BS(buf);
        #pragma unroll
        for (int i = 0; i < 4; i++) {
            int idx = t + 256 * i;          // 1024 chunks of 16B
            int m = idx >> 3, ch = idx & 7;
            cp16(Ab + m * 36 + ch * 4, x + (row0 + m) * EMB + k0 + ch * 4);
        }
        #pragma unroll
        for (int i = 0; i < 2; i++) {
            int idx = t + 256 * i;          // 512 chunks
            int k = idx >> 4, ch = idx & 15;
            cp16(Bb + k * 72 + ch * 4, W + (k0 + k) * HEAD + ch * 4);
        }
    };

    float acc[2][4][4] = {};

    prefetch(0, 0);
    CP_COMMIT();

    for (int step = 0; step < 32; step++) {
        const int cur = step & 1;
        CP_WAIT0();
        __syncthreads();
        if (step < 31) { prefetch((step + 1) * 32, cur ^ 1); CP_COMMIT(); }

        const float* Ab = QKV_AS(cur);
        const float* Bb = QKV_BS(cur);

        #pragma unroll
        for (int ks = 0; ks < 4; ks++) {
            uint32_t afrag[2][4];
            #pragma unroll
            for (int mt = 0; mt < 2; mt++) {
                const float* ap = Ab + (m0 + mt * 16 + r) * 36 + ks * 8 + c;
                afrag[mt][0] = f2tf(ap[0]);
                afrag[mt][1] = f2tf(ap[8 * 36]);
                afrag[mt][2] = f2tf(ap[4]);
                afrag[mt][3] = f2tf(ap[8 * 36 + 4]);
            }
            #pragma unroll
            for (int nt = 0; nt < 4; nt++) {
                uint32_t bfrag[2];
                const float* bp = Bb + (ks * 8 + c) * 72 + n0 + nt * 8 + r;
                bfrag[0] = f2tf(bp[0]);
                bfrag[1] = f2tf(bp[4 * 72]);
                mma_tf32(acc[0][nt], afrag[0], bfrag);
                mma_tf32(acc[1][nt], afrag[1], bfrag);
            }
        }
        __syncthreads();
    }

    // ---- epilogue: +bias; K/V written pre-rounded to tf32 (RNA) ----
    const bool roundout = (which != 0);
    #pragma unroll
    for (int mt = 0; mt < 2; mt++) {
        #pragma unroll
        for (int nt = 0; nt < 4; nt++) {
            int n = n0 + nt * 8 + 2 * c;
            float b0 = bias[n], b1 = bias[n + 1];
            int mA = row0 + m0 + mt * 16 + r;
            float v00 = acc[mt][nt][0] + b0, v01 = acc[mt][nt][1] + b1;
            float v10 = acc[mt][nt][2] + b0, v11 = acc[mt][nt][3] + b1;
            if (roundout) {
                v00 = __uint_as_float(f2tf(v00));
                v01 = __uint_as_float(f2tf(v01));
                v10 = __uint_as_float(f2tf(v10));
                v11 = __uint_as_float(f2tf(v11));
            }
            *(float2*)&out[mA * HEAD + n]       = make_float2(v00, v01);
            *(float2*)&out[(mA + 8) * HEAD + n] = make_float2(v10, v11);
        }
    }
}

// ---------------------------------------------------------------------------
// Kernel 2: causal flash attention.  BQ=64, BK=64, 128 thr (4 warps x 16 rows)
// Ks: [key][d] stride 68, Vs: [key][d] stride 72, double-buffered cp.async.
// K/V already tf32-valued in gmem -> consumed raw (HW truncation lossless).
// Ps: per-warp slab [16][68] (RNA tf32 P after softmax).
// Work remap pairs co-resident blocks (bid, bid+148 same SM) to ~55 iters.
// ---------------------------------------------------------------------------
#define ATT_KS(buf) (sm + (buf) * 4352)            // 64*68
#define ATT_VS(buf) (sm + 8704 + (buf) * 4608)     // 64*72
#define ATT_PS      (sm + 17920)                   // + warp*1088
#define ATT_SMEM_BYTES 89088

__global__ __launch_bounds__(128) void attn_kernel(float* __restrict__ out)
{
    extern __shared__ float sm[];

    const float* Q = g_QKV[0];
    const float* K = g_QKV[1];
    const float* V = g_QKV[2];

    // ---- work remap for SM pairing ----
    const int lid = blockIdx.x + 64 * blockIdx.y;   // 0..255
    int qb, b;
    if (lid < 108)        { qb = 53 - (lid >> 2);          b = lid & 3; }
    else if (lid < 148)   { int k = lid - 108; qb = 63 - (k >> 2); b = k & 3; }
    else                  { int k = lid - 148; qb = k >> 2;        b = k & 3; }

    const int t    = threadIdx.x;
    const int lane = t & 31;
    const int warp = t >> 5;
    const int base = b * S_LEN * HEAD;

    const int r = lane >> 2;
    const int c = lane & 3;

    float* Psw = ATT_PS + warp * 1088;

    auto prefetch = [&](int kb, int buf) {
        const float* Kg = K + base + kb * 64 * HEAD;
        const float* Vg = V + base + kb * 64 * HEAD;
        float* Kb = ATT_KS(buf);
        float* Vb = ATT_VS(buf);
        #pragma unroll
        for (int i = 0; i < 8; i++) {
            int idx = t + 128 * i;          // 1024 chunks each
            int row = idx >> 4, ch = idx & 15;
            cp16(Kb + row * 68 + ch * 4, Kg + row * 64 + ch * 4);
            cp16(Vb + row * 72 + ch * 4, Vg + row * 64 + ch * 4);
        }
    };

    // ---- Q fragments in registers (scaled, RNA tf32) ----
    uint32_t qa[8][4];
    {
        const int qrow = qb * 64 + warp * 16 + r;
        #pragma unroll
        for (int kt = 0; kt < 8; kt++) {
            int d = kt * 8 + c;
            qa[kt][0] = f2tf(Q[base + qrow * HEAD + d] * 0.125f);
            qa[kt][1] = f2tf(Q[base + (qrow + 8) * HEAD + d] * 0.125f);
            qa[kt][2] = f2tf(Q[base + qrow * HEAD + d + 4] * 0.125f);
            qa[kt][3] = f2tf(Q[base + (qrow + 8) * HEAD + d + 4] * 0.125f);
        }
    }

    float oacc[8][4] = {};
    float mA = -1e30f, mB = -1e30f, lA = 0.0f, lB = 0.0f;

    prefetch(0, 0);
    CP_COMMIT();

    for (int kb = 0; kb <= qb; kb++) {
        const int cur = kb & 1;
        CP_WAIT0();
        __syncthreads();               // buf cur ready; buf cur^1 free
        if (kb < qb) { prefetch(kb + 1, cur ^ 1); CP_COMMIT(); }

        const float* Kb = ATT_KS(cur);
        const float* Vb = ATT_VS(cur);

        // ---- S = Q K^T (K values already tf32 -> raw reads) ----
        float sacc[8][4] = {};
        #pragma unroll
        for (int dk = 0; dk < 8; dk++) {
            #pragma unroll
            for (int nt = 0; nt < 8; nt++) {
                uint32_t bfrag[2];
                const float* kp = Kb + (nt * 8 + r) * 68 + dk * 8 + c;
                bfrag[0] = __float_as_uint(kp[0]);
                bfrag[1] = __float_as_uint(kp[4]);
                mma_tf32(sacc[nt], qa[dk], bfrag);
            }
        }

        // ---- causal mask on diagonal block ----
        if (kb == qb) {
            int qA = warp * 16 + r;
            int qB = qA + 8;
            #pragma unroll
            for (int nt = 0; nt < 8; nt++) {
                int k0l = nt * 8 + 2 * c;
                if (k0l     > qA) sacc[nt][0] = -1e30f;
                if (k0l + 1 > qA) sacc[nt][1] = -1e30f;
                if (k0l     > qB) sacc[nt][2] = -1e30f;
                if (k0l + 1 > qB) sacc[nt][3] = -1e30f;
            }
        }

        // ---- online softmax ----
        {
            float mxA = -1e30f, mxB = -1e30f;
            #pragma unroll
            for (int nt = 0; nt < 8; nt++) {
                mxA = fmaxf(mxA, fmaxf(sacc[nt][0], sacc[nt][1]));
                mxB = fmaxf(mxB, fmaxf(sacc[nt][2], sacc[nt][3]));
            }
            mxA = fmaxf(mxA, __shfl_xor_sync(0xffffffffu, mxA, 1, 4));
            mxA = fmaxf(mxA, __shfl_xor_sync(0xffffffffu, mxA, 2, 4));
            mxB = fmaxf(mxB, __shfl_xor_sync(0xffffffffu, mxB, 1, 4));
            mxB = fmaxf(mxB, __shfl_xor_sync(0xffffffffu, mxB, 2, 4));
            float mnA = fmaxf(mA, mxA);
            float mnB = fmaxf(mB, mxB);
            float alA = __expf(mA - mnA);
            float alB = __expf(mB - mnB);
            mA = mnA; mB = mnB;
            float rsA = 0.0f, rsB = 0.0f;
            #pragma unroll
            for (int nt = 0; nt < 8; nt++) {
                sacc[nt][0] = __expf(sacc[nt][0] - mnA);
                sacc[nt][1] = __expf(sacc[nt][1] - mnA);
                sacc[nt][2] = __expf(sacc[nt][2] - mnB);
                sacc[nt][3] = __expf(sacc[nt][3] - mnB);
                rsA += sacc[nt][0] + sacc[nt][1];
                rsB += sacc[nt][2] + sacc[nt][3];
            }
            rsA += __shfl_xor_sync(0xffffffffu, rsA, 1, 4);
            rsA += __shfl_xor_sync(0xffffffffu, rsA, 2, 4);
            rsB += __shfl_xor_sync(0xffffffffu, rsB, 1, 4);
            rsB += __shfl_xor_sync(0xffffffffu, rsB, 2, 4);
            lA = lA * alA + rsA;
            lB = lB * alB + rsB;
            #pragma unroll
            for (int dt = 0; dt < 8; dt++) {
                oacc[dt][0] *= alA; oacc[dt][1] *= alA;
                oacc[dt][2] *= alB; oacc[dt][3] *= alB;
            }
        }

        // ---- P into own warp slab (RNA tf32) ----
        #pragma unroll
        for (int nt = 0; nt < 8; nt++) {
            int col = nt * 8 + 2 * c;
            uint2 p0, p1;
            p0.x = f2tf(sacc[nt][0]); p0.y = f2tf(sacc[nt][1]);
            p1.x = f2tf(sacc[nt][2]); p1.y = f2tf(sacc[nt][3]);
            *(uint2*)&Psw[r * 68 + col]       = p0;
            *(uint2*)&Psw[(r + 8) * 68 + col] = p1;
        }
        __syncwarp();

        // ---- O += P V (V values already tf32 -> raw reads) ----
        #pragma unroll
        for (int kt = 0; kt < 8; kt++) {
            uint32_t pa[4];
            pa[0] = __float_as_uint(Psw[r * 68 + kt * 8 + c]);
            pa[1] = __float_as_uint(Psw[(r + 8) * 68 + kt * 8 + c]);
            pa[2] = __float_as_uint(Psw[r * 68 + kt * 8 + c + 4]);
            pa[3] = __float_as_uint(Psw[(r + 8) * 68 + kt * 8 + c + 4]);
            #pragma unroll
            for (int dt = 0; dt < 8; dt++) {
                uint32_t vb[2];
                const float* vp = Vb + (kt * 8 + c) * 72 + dt * 8 + r;
                vb[0] = __float_as_uint(vp[0]);
                vb[1] = __float_as_uint(vp[4 * 72]);
                mma_tf32(oacc[dt], pa, vb);
            }
        }
        __syncthreads();               // all warps done with buf cur
    }

    // ---- epilogue ----
    {
        float invA = 1.0f / lA;
        float invB = 1.0f / lB;
        int qrow = qb * 64 + warp * 16 + r;
        #pragma unroll
        for (int dt = 0; dt < 8; dt++) {
            int d = dt * 8 + 2 * c;
            *(float2*)&out[base + qrow * HEAD + d] =
                make_float2(oacc[dt][0] * invA, oacc[dt][1] * invA);
            *(float2*)&out[base + (qrow + 8) * HEAD + d] =
                make_float2(oacc[dt][2] * invB, oacc[dt][3] * invB);
        }
    }
}

// ---------------------------------------------------------------------------
extern "C" void kernel_launch(void* const* d_in, const int* in_sizes, int n_in,
                              void* d_out, int out_size)
{
    const float* x  = (const float*)d_in[0];
    const float* Wq = (const float*)d_in[1];
    const float* bq = (const float*)d_in[2];
    const float* Wk = (const float*)d_in[3];
    const float* bk = (const float*)d_in[4];
    const float* Wv = (const float*)d_in[5];
    const float* bv = (const float*)d_in[6];
    float* out = (float*)d_out;

    cudaFuncSetAttribute(qkv_kernel,
        cudaFuncAttributeMaxDynamicSharedMemorySize, QKV_SMEM_BYTES);
    cudaFuncSetAttribute(attn_kernel,
        cudaFuncAttributeMaxDynamicSharedMemorySize, ATT_SMEM_BYTES);

    dim3 g1(M_TOTAL / 128, 3);
    qkv_kernel<<<g1, 256, QKV_SMEM_BYTES>>>(x, Wq, bq, Wk, bk, Wv, bv);

    dim3 g2(S_LEN / 64, BATCH);
    attn_kernel<<<g2, 128, ATT_SMEM_BYTES>>>(out);
}

// round 6
// speedup vs baseline: 4.5733x; 1.2475x over previous
#include <cuda_runtime.h>
#include <cstdint>

#define S_LEN 4096
#define EMB   1024
#define HEAD  64
#define BATCH 4
#define M_TOTAL (BATCH * S_LEN)   // 16384

__device__ float g_QKV[3][M_TOTAL * HEAD];

// ---------------------------------------------------------------------------
// helpers
// ---------------------------------------------------------------------------
__device__ __forceinline__ uint32_t f2tf(float f) {
    uint32_t r;
    asm("cvt.rna.tf32.f32 %0, %1;" : "=r"(r) : "f"(f));
    return r;
}

__device__ __forceinline__ void mma_tf32(float c[4],
                                         const uint32_t a[4],
                                         const uint32_t b[2]) {
    asm volatile(
        "mma.sync.aligned.m16n8k8.row.col.f32.tf32.tf32.f32 "
        "{%0,%1,%2,%3}, {%4,%5,%6,%7}, {%8,%9}, {%0,%1,%2,%3};\n"
        : "+f"(c[0]), "+f"(c[1]), "+f"(c[2]), "+f"(c[3])
        : "r"(a[0]), "r"(a[1]), "r"(a[2]), "r"(a[3]),
          "r"(b[0]), "r"(b[1]));
}

__device__ __forceinline__ void cp16(float* s, const float* g) {
    uint32_t sa = (uint32_t)__cvta_generic_to_shared(s);
    asm volatile("cp.async.cg.shared.global [%0], [%1], 16;\n"
                 :: "r"(sa), "l"(g));
}
#define CP_COMMIT() asm volatile("cp.async.commit_group;\n")
#define CP_WAIT0()  asm volatile("cp.async.wait_group 0;\n")
#define CP_WAIT1()  asm volatile("cp.async.wait_group 1;\n")

__device__ __forceinline__ void barg(int g) {   // per-group named barrier
    asm volatile("bar.sync %0, 128;" :: "r"(g + 1) : "memory");
}

// ---------------------------------------------------------------------------
// Kernel 1: QKV projection (unchanged from R5: RNA in-register, K/V outputs
// pre-rounded to tf32 so attention consumes them raw).
// ---------------------------------------------------------------------------
#define QKV_AS(buf)  (sm + (buf) * 4608)          // 128*36
#define QKV_BS(buf)  (sm + 9216 + (buf) * 2304)   // 32*72
#define QKV_SMEM_BYTES 55296

__global__ __launch_bounds__(256) void qkv_kernel(
    const float* __restrict__ x,
    const float* __restrict__ Wq, const float* __restrict__ bq,
    const float* __restrict__ Wk, const float* __restrict__ bk,
    const float* __restrict__ Wv, const float* __restrict__ bv)
{
    extern __shared__ float sm[];

    const int which = blockIdx.y;
    const float* W    = (which == 0) ? Wq : (which == 1) ? Wk : Wv;
    const float* bias = (which == 0) ? bq : (which == 1) ? bk : bv;
    float* out = g_QKV[which];

    const int t    = threadIdx.x;
    const int lane = t & 31;
    const int warp = t >> 5;
    const int m0   = (warp >> 1) * 32;
    const int n0   = (warp & 1) * 32;
    const int row0 = blockIdx.x * 128;

    const int r = lane >> 2;
    const int c = lane & 3;

    auto prefetch = [&](int k0, int buf) {
        float* Ab = QKV_AS(buf);
        float* Bb = QKV_BS(buf);
        #pragma unroll
        for (int i = 0; i < 4; i++) {
            int idx = t + 256 * i;
            int m = idx >> 3, ch = idx & 7;
            cp16(Ab + m * 36 + ch * 4, x + (row0 + m) * EMB + k0 + ch * 4);
        }
        #pragma unroll
        for (int i = 0; i < 2; i++) {
            int idx = t + 256 * i;
            int k = idx >> 4, ch = idx & 15;
            cp16(Bb + k * 72 + ch * 4, W + (k0 + k) * HEAD + ch * 4);
        }
    };

    float acc[2][4][4] = {};

    prefetch(0, 0);
    CP_COMMIT();

    for (int step = 0; step < 32; step++) {
        const int cur = step & 1;
        CP_WAIT0();
        __syncthreads();
        if (step < 31) { prefetch((step + 1) * 32, cur ^ 1); CP_COMMIT(); }

        const float* Ab = QKV_AS(cur);
        const float* Bb = QKV_BS(cur);

        #pragma unroll
        for (int ks = 0; ks < 4; ks++) {
            uint32_t afrag[2][4];
            #pragma unroll
            for (int mt = 0; mt < 2; mt++) {
                const float* ap = Ab + (m0 + mt * 16 + r) * 36 + ks * 8 + c;
                afrag[mt][0] = f2tf(ap[0]);
                afrag[mt][1] = f2tf(ap[8 * 36]);
                afrag[mt][2] = f2tf(ap[4]);
                afrag[mt][3] = f2tf(ap[8 * 36 + 4]);
            }
            #pragma unroll
            for (int nt = 0; nt < 4; nt++) {
                uint32_t bfrag[2];
                const float* bp = Bb + (ks * 8 + c) * 72 + n0 + nt * 8 + r;
                bfrag[0] = f2tf(bp[0]);
                bfrag[1] = f2tf(bp[4 * 72]);
                mma_tf32(acc[0][nt], afrag[0], bfrag);
                mma_tf32(acc[1][nt], afrag[1], bfrag);
            }
        }
        __syncthreads();
    }

    const bool roundout = (which != 0);
    #pragma unroll
    for (int mt = 0; mt < 2; mt++) {
        #pragma unroll
        for (int nt = 0; nt < 4; nt++) {
            int n = n0 + nt * 8 + 2 * c;
            float b0 = bias[n], b1 = bias[n + 1];
            int mA = row0 + m0 + mt * 16 + r;
            float v00 = acc[mt][nt][0] + b0, v01 = acc[mt][nt][1] + b1;
            float v10 = acc[mt][nt][2] + b0, v11 = acc[mt][nt][3] + b1;
            if (roundout) {
                v00 = __uint_as_float(f2tf(v00));
                v01 = __uint_as_float(f2tf(v01));
                v10 = __uint_as_float(f2tf(v10));
                v11 = __uint_as_float(f2tf(v11));
            }
            *(float2*)&out[mA * HEAD + n]       = make_float2(v00, v01);
            *(float2*)&out[(mA + 8) * HEAD + n] = make_float2(v10, v11);
        }
    }
}

// ---------------------------------------------------------------------------
// Kernel 2: causal flash attention, IN-BLOCK SPLIT-KV.
// 256 threads = 2 groups x 4 warps, both over the same BQ=64 query rows.
// Group g handles kb = g, g+2, ...  (own m/l/O state; merged at the end).
// Per group: K [64][68] single-buf, V [64][72] single-buf; deferred prefetch
// (K(kb+2) after S, V(kb+2) after PV) + wait_group-1 alternation for overlap.
// P: per-warp slab [16][68]. Merge scratch aliases group-0 K/V (dead).
// smem = 106496 B -> 2 blocks/SM = 16 warps/SM.
// ---------------------------------------------------------------------------
#define ATT_KG(g)   (sm + (g) * 8960)             // 64*68 floats
#define ATT_VG(g)   (sm + (g) * 8960 + 4352)      // 64*72 floats
#define ATT_PS      (sm + 17920)                  // + warp*1088
#define ATT_SMEM_BYTES 106496

__global__ __launch_bounds__(256, 2) void attn_kernel(float* __restrict__ out)
{
    extern __shared__ float sm[];

    const float* Q = g_QKV[0];
    const float* K = g_QKV[1];
    const float* V = g_QKV[2];

    // ---- work remap for SM pairing (cost ~ (qb+1)/2 now, same ordering) ----
    const int lid = blockIdx.x + 64 * blockIdx.y;   // 0..255
    int qb, b;
    if (lid < 108)        { qb = 53 - (lid >> 2);          b = lid & 3; }
    else if (lid < 148)   { int k = lid - 108; qb = 63 - (k >> 2); b = k & 3; }
    else                  { int k = lid - 148; qb = k >> 2;        b = k & 3; }

    const int t    = threadIdx.x;
    const int lane = t & 31;
    const int warp = t >> 5;
    const int g    = warp >> 2;        // split-KV group 0/1
    const int lw   = warp & 3;         // warp within group
    const int t128 = t & 127;
    const int base = b * S_LEN * HEAD;

    const int r = lane >> 2;
    const int c = lane & 3;

    float* Kb  = ATT_KG(g);
    float* Vb  = ATT_VG(g);
    float* Psw = ATT_PS + warp * 1088;

    auto pfK = [&](int kb) {
        const float* Kg = K + base + kb * 64 * HEAD;
        #pragma unroll
        for (int i = 0; i < 8; i++) {
            int idx = t128 + 128 * i;
            int row = idx >> 4, ch = idx & 15;
            cp16(Kb + row * 68 + ch * 4, Kg + row * 64 + ch * 4);
        }
    };
    auto pfV = [&](int kb) {
        const float* Vg = V + base + kb * 64 * HEAD;
        #pragma unroll
        for (int i = 0; i < 8; i++) {
            int idx = t128 + 128 * i;
            int row = idx >> 4, ch = idx & 15;
            cp16(Vb + row * 72 + ch * 4, Vg + row * 64 + ch * 4);
        }
    };

    // ---- Q fragments (both groups load the same rows; RNA tf32, scaled) ----
    uint32_t qa[8][4];
    {
        const int qrow = qb * 64 + lw * 16 + r;
        #pragma unroll
        for (int kt = 0; kt < 8; kt++) {
            int d = kt * 8 + c;
            qa[kt][0] = f2tf(Q[base + qrow * HEAD + d] * 0.125f);
            qa[kt][1] = f2tf(Q[base + (qrow + 8) * HEAD + d] * 0.125f);
            qa[kt][2] = f2tf(Q[base + qrow * HEAD + d + 4] * 0.125f);
            qa[kt][3] = f2tf(Q[base + (qrow + 8) * HEAD + d + 4] * 0.125f);
        }
    }

    float oacc[8][4] = {};
    float mA = -1e30f, mB = -1e30f, lA = 0.0f, lB = 0.0f;

    if (g <= qb) {
        pfK(g); CP_COMMIT();
        pfV(g); CP_COMMIT();
    }

    for (int kb = g; kb <= qb; kb += 2) {
        CP_WAIT1();            // K(kb) done (V may trail)
        barg(g);

        // ---- S = Q K^T ----
        float sacc[8][4] = {};
        #pragma unroll
        for (int dk = 0; dk < 8; dk++) {
            #pragma unroll
            for (int nt = 0; nt < 8; nt++) {
                uint32_t bfrag[2];
                const float* kp = Kb + (nt * 8 + r) * 68 + dk * 8 + c;
                bfrag[0] = __float_as_uint(kp[0]);
                bfrag[1] = __float_as_uint(kp[4]);
                mma_tf32(sacc[nt], qa[dk], bfrag);
            }
        }

        barg(g);               // all group warps done reading K(kb)
        if (kb + 2 <= qb) pfK(kb + 2);
        CP_COMMIT();           // commit even when empty (keeps wait counts)

        // ---- causal mask on diagonal block ----
        if (kb == qb) {
            int qA = lw * 16 + r;
            int qB = qA + 8;
            #pragma unroll
            for (int nt = 0; nt < 8; nt++) {
                int k0l = nt * 8 + 2 * c;
                if (k0l     > qA) sacc[nt][0] = -1e30f;
                if (k0l + 1 > qA) sacc[nt][1] = -1e30f;
                if (k0l     > qB) sacc[nt][2] = -1e30f;
                if (k0l + 1 > qB) sacc[nt][3] = -1e30f;
            }
        }

        // ---- online softmax ----
        {
            float mxA = -1e30f, mxB = -1e30f;
            #pragma unroll
            for (int nt = 0; nt < 8; nt++) {
                mxA = fmaxf(mxA, fmaxf(sacc[nt][0], sacc[nt][1]));
                mxB = fmaxf(mxB, fmaxf(sacc[nt][2], sacc[nt][3]));
            }
            mxA = fmaxf(mxA, __shfl_xor_sync(0xffffffffu, mxA, 1, 4));
            mxA = fmaxf(mxA, __shfl_xor_sync(0xffffffffu, mxA, 2, 4));
            mxB = fmaxf(mxB, __shfl_xor_sync(0xffffffffu, mxB, 1, 4));
            mxB = fmaxf(mxB, __shfl_xor_sync(0xffffffffu, mxB, 2, 4));
            float mnA = fmaxf(mA, mxA);
            float mnB = fmaxf(mB, mxB);
            float alA = __expf(mA - mnA);
            float alB = __expf(mB - mnB);
            mA = mnA; mB = mnB;
            float rsA = 0.0f, rsB = 0.0f;
            #pragma unroll
            for (int nt = 0; nt < 8; nt++) {
                sacc[nt][0] = __expf(sacc[nt][0] - mnA);
                sacc[nt][1] = __expf(sacc[nt][1] - mnA);
                sacc[nt][2] = __expf(sacc[nt][2] - mnB);
                sacc[nt][3] = __expf(sacc[nt][3] - mnB);
                rsA += sacc[nt][0] + sacc[nt][1];
                rsB += sacc[nt][2] + sacc[nt][3];
            }
            rsA += __shfl_xor_sync(0xffffffffu, rsA, 1, 4);
            rsA += __shfl_xor_sync(0xffffffffu, rsA, 2, 4);
            rsB += __shfl_xor_sync(0xffffffffu, rsB, 1, 4);
            rsB += __shfl_xor_sync(0xffffffffu, rsB, 2, 4);
            lA = lA * alA + rsA;
            lB = lB * alB + rsB;
            #pragma unroll
            for (int dt = 0; dt < 8; dt++) {
                oacc[dt][0] *= alA; oacc[dt][1] *= alA;
                oacc[dt][2] *= alB; oacc[dt][3] *= alB;
            }
        }

        // ---- P into own warp slab (RNA tf32) ----
        #pragma unroll
        for (int nt = 0; nt < 8; nt++) {
            int col = nt * 8 + 2 * c;
            uint2 p0, p1;
            p0.x = f2tf(sacc[nt][0]); p0.y = f2tf(sacc[nt][1]);
            p1.x = f2tf(sacc[nt][2]); p1.y = f2tf(sacc[nt][3]);
            *(uint2*)&Psw[r * 68 + col]       = p0;
            *(uint2*)&Psw[(r + 8) * 68 + col] = p1;
        }
        __syncwarp();

        CP_WAIT1();            // V(kb) done (K(kb+2) may trail)
        barg(g);

        // ---- O += P V ----
        #pragma unroll
        for (int kt = 0; kt < 8; kt++) {
            uint32_t pa[4];
            pa[0] = __float_as_uint(Psw[r * 68 + kt * 8 + c]);
            pa[1] = __float_as_uint(Psw[(r + 8) * 68 + kt * 8 + c]);
            pa[2] = __float_as_uint(Psw[r * 68 + kt * 8 + c + 4]);
            pa[3] = __float_as_uint(Psw[(r + 8) * 68 + kt * 8 + c + 4]);
            #pragma unroll
            for (int dt = 0; dt < 8; dt++) {
                uint32_t vb[2];
                const float* vp = Vb + (kt * 8 + c) * 72 + dt * 8 + r;
                vb[0] = __float_as_uint(vp[0]);
                vb[1] = __float_as_uint(vp[4 * 72]);
                mma_tf32(oacc[dt], pa, vb);
            }
        }

        barg(g);               // all group warps done reading V(kb)
        if (kb + 2 <= qb) pfV(kb + 2);
        CP_COMMIT();
    }

    // ---- merge the two split-KV partials (scratch aliases group-0 K/V) ----
    float* MS = sm;            // 128 threads x 37 floats = 18944 B < 35840 B
    __syncthreads();           // both groups finished their loops
    if (g == 1) {
        float* p = MS + t128 * 37;
        #pragma unroll
        for (int dt = 0; dt < 8; dt++) {
            p[dt * 4 + 0] = oacc[dt][0]; p[dt * 4 + 1] = oacc[dt][1];
            p[dt * 4 + 2] = oacc[dt][2]; p[dt * 4 + 3] = oacc[dt][3];
        }
        p[32] = mA; p[33] = mB; p[34] = lA; p[35] = lB;
    }
    __syncthreads();
    if (g == 0) {
        const float* p = MS + t128 * 37;
        float m1A = p[32], m1B = p[33], l1A = p[34], l1B = p[35];
        float mnA = fmaxf(mA, m1A);
        float mnB = fmaxf(mB, m1B);
        float w0A = __expf(mA - mnA), w1A = __expf(m1A - mnA);
        float w0B = __expf(mB - mnB), w1B = __expf(m1B - mnB);
        float invA = 1.0f / (lA * w0A + l1A * w1A);
        float invB = 1.0f / (lB * w0B + l1B * w1B);
        int qrow = qb * 64 + lw * 16 + r;
        #pragma unroll
        for (int dt = 0; dt < 8; dt++) {
            float o0 = (oacc[dt][0] * w0A + p[dt * 4 + 0] * w1A) * invA;
            float o1 = (oacc[dt][1] * w0A + p[dt * 4 + 1] * w1A) * invA;
            float o2 = (oacc[dt][2] * w0B + p[dt * 4 + 2] * w1B) * invB;
            float o3 = (oacc[dt][3] * w0B + p[dt * 4 + 3] * w1B) * invB;
            int d = dt * 8 + 2 * c;
            *(float2*)&out[base + qrow * HEAD + d]       = make_float2(o0, o1);
            *(float2*)&out[base + (qrow + 8) * HEAD + d] = make_float2(o2, o3);
        }
    }
}

// ---------------------------------------------------------------------------
extern "C" void kernel_launch(void* const* d_in, const int* in_sizes, int n_in,
                              void* d_out, int out_size)
{
    const float* x  = (const float*)d_in[0];
    const float* Wq = (const float*)d_in[1];
    const float* bq = (const float*)d_in[2];
    const float* Wk = (const float*)d_in[3];
    const float* bk = (const float*)d_in[4];
    const float* Wv = (const float*)d_in[5];
    const float* bv = (const float*)d_in[6];
    float* out = (float*)d_out;

    cudaFuncSetAttribute(qkv_kernel,
        cudaFuncAttributeMaxDynamicSharedMemorySize, QKV_SMEM_BYTES);
    cudaFuncSetAttribute(attn_kernel,
        cudaFuncAttributeMaxDynamicSharedMemorySize, ATT_SMEM_BYTES);

    dim3 g1(M_TOTAL / 128, 3);
    qkv_kernel<<<g1, 256, QKV_SMEM_BYTES>>>(x, Wq, bq, Wk, bk, Wv, bv);

    dim3 g2(S_LEN / 64, BATCH);
    attn_kernel<<<g2, 256, ATT_SMEM_BYTES>>>(out);
}

// round 7
// speedup vs baseline: 4.5954x; 1.0048x over previous
#include <cuda_runtime.h>
#include <cstdint>

#define S_LEN 4096
#define EMB   1024
#define HEAD  64
#define BATCH 4
#define M_TOTAL (BATCH * S_LEN)   // 16384

__device__ float g_QKV[3][M_TOTAL * HEAD];

// ---------------------------------------------------------------------------
// helpers
// ---------------------------------------------------------------------------
__device__ __forceinline__ uint32_t f2tf(float f) {
    uint32_t r;
    asm("cvt.rna.tf32.f32 %0, %1;" : "=r"(r) : "f"(f));
    return r;
}

__device__ __forceinline__ void mma_tf32(float c[4],
                                         const uint32_t a[4],
                                         const uint32_t b[2]) {
    asm volatile(
        "mma.sync.aligned.m16n8k8.row.col.f32.tf32.tf32.f32 "
        "{%0,%1,%2,%3}, {%4,%5,%6,%7}, {%8,%9}, {%0,%1,%2,%3};\n"
        : "+f"(c[0]), "+f"(c[1]), "+f"(c[2]), "+f"(c[3])
        : "r"(a[0]), "r"(a[1]), "r"(a[2]), "r"(a[3]),
          "r"(b[0]), "r"(b[1]));
}

__device__ __forceinline__ void cp16(float* s, const float* g) {
    uint32_t sa = (uint32_t)__cvta_generic_to_shared(s);
    asm volatile("cp.async.cg.shared.global [%0], [%1], 16;\n"
                 :: "r"(sa), "l"(g));
}
#define CP_COMMIT() asm volatile("cp.async.commit_group;\n")
#define CP_WAIT0()  asm volatile("cp.async.wait_group 0;\n")
#define CP_WAIT1()  asm volatile("cp.async.wait_group 1;\n")

__device__ __forceinline__ void barg(int g) {   // per-group named barrier
    asm volatile("bar.sync %0, 128;" :: "r"(g + 1) : "memory");
}

// ---------------------------------------------------------------------------
// Kernel 1: QKV projection.
// Q written natural (raw fp32).
// K written RNA-tf32 with COLUMN-PAIR permutation: within each 8-col group,
//   logical d stored at 2*(d&3) + (d>>2)  -> attn b-frag (d=c, d=c+4) is one
//   contiguous float2.
// V written RNA-tf32 with ROW-PAIR interleave into g_QKV[2]:
//   element (m, d) at (m>>3)*512 + (m&3)*128 + 2*d + ((m>>2)&1)
//   -> attn b-frag (k=c, k=c+4) is one contiguous float2.
// ---------------------------------------------------------------------------
#define QKV_AS(buf)  (sm + (buf) * 4608)          // 128*36
#define QKV_BS(buf)  (sm + 9216 + (buf) * 2304)   // 32*72
#define QKV_SMEM_BYTES 55296

__global__ __launch_bounds__(256) void qkv_kernel(
    const float* __restrict__ x,
    const float* __restrict__ Wq, const float* __restrict__ bq,
    const float* __restrict__ Wk, const float* __restrict__ bk,
    const float* __restrict__ Wv, const float* __restrict__ bv)
{
    extern __shared__ float sm[];

    const int which = blockIdx.y;
    const float* W    = (which == 0) ? Wq : (which == 1) ? Wk : Wv;
    const float* bias = (which == 0) ? bq : (which == 1) ? bk : bv;
    float* out = g_QKV[which];

    const int t    = threadIdx.x;
    const int lane = t & 31;
    const int warp = t >> 5;
    const int m0   = (warp >> 1) * 32;
    const int n0   = (warp & 1) * 32;
    const int row0 = blockIdx.x * 128;

    const int r = lane >> 2;
    const int c = lane & 3;

    auto prefetch = [&](int k0, int buf) {
        float* Ab = QKV_AS(buf);
        float* Bb = QKV_BS(buf);
        #pragma unroll
        for (int i = 0; i < 4; i++) {
            int idx = t + 256 * i;
            int m = idx >> 3, ch = idx & 7;
            cp16(Ab + m * 36 + ch * 4, x + (row0 + m) * EMB + k0 + ch * 4);
        }
        #pragma unroll
        for (int i = 0; i < 2; i++) {
            int idx = t + 256 * i;
            int k = idx >> 4, ch = idx & 15;
            cp16(Bb + k * 72 + ch * 4, W + (k0 + k) * HEAD + ch * 4);
        }
    };

    float acc[2][4][4] = {};

    prefetch(0, 0);
    CP_COMMIT();

    for (int step = 0; step < 32; step++) {
        const int cur = step & 1;
        CP_WAIT0();
        __syncthreads();
        if (step < 31) { prefetch((step + 1) * 32, cur ^ 1); CP_COMMIT(); }

        const float* Ab = QKV_AS(cur);
        const float* Bb = QKV_BS(cur);

        #pragma unroll
        for (int ks = 0; ks < 4; ks++) {
            uint32_t afrag[2][4];
            #pragma unroll
            for (int mt = 0; mt < 2; mt++) {
                const float* ap = Ab + (m0 + mt * 16 + r) * 36 + ks * 8 + c;
                afrag[mt][0] = f2tf(ap[0]);
                afrag[mt][1] = f2tf(ap[8 * 36]);
                afrag[mt][2] = f2tf(ap[4]);
                afrag[mt][3] = f2tf(ap[8 * 36 + 4]);
            }
            #pragma unroll
            for (int nt = 0; nt < 4; nt++) {
                uint32_t bfrag[2];
                const float* bp = Bb + (ks * 8 + c) * 72 + n0 + nt * 8 + r;
                bfrag[0] = f2tf(bp[0]);
                bfrag[1] = f2tf(bp[4 * 72]);
                mma_tf32(acc[0][nt], afrag[0], bfrag);
                mma_tf32(acc[1][nt], afrag[1], bfrag);
            }
        }
        __syncthreads();
    }

    // ---- epilogue ----
    const int j  = 2 * c;                    // column pair base within group
    const int p0 = 2 * (j & 3) + (j >> 2);   // K permutation targets
    const int p1 = 2 * ((j + 1) & 3) + ((j + 1) >> 2);

    #pragma unroll
    for (int mt = 0; mt < 2; mt++) {
        #pragma unroll
        for (int nt = 0; nt < 4; nt++) {
            int n = n0 + nt * 8 + 2 * c;
            float b0 = bias[n], b1 = bias[n + 1];
            int mA = row0 + m0 + mt * 16 + r;
            float v00 = acc[mt][nt][0] + b0, v01 = acc[mt][nt][1] + b1;
            float v10 = acc[mt][nt][2] + b0, v11 = acc[mt][nt][3] + b1;

            if (which == 0) {
                *(float2*)&out[mA * HEAD + n]       = make_float2(v00, v01);
                *(float2*)&out[(mA + 8) * HEAD + n] = make_float2(v10, v11);
            } else if (which == 1) {
                // K: rounded, column-pair permuted within the 8-col group
                int base8 = n0 + nt * 8;
                out[mA * HEAD + base8 + p0]       = __uint_as_float(f2tf(v00));
                out[mA * HEAD + base8 + p1]       = __uint_as_float(f2tf(v01));
                out[(mA + 8) * HEAD + base8 + p0] = __uint_as_float(f2tf(v10));
                out[(mA + 8) * HEAD + base8 + p1] = __uint_as_float(f2tf(v11));
            } else {
                // V: rounded, row-pair interleaved layout
                int mB = mA + 8;
                int baseA = (mA >> 3) * 512 + (mA & 3) * 128 + ((mA >> 2) & 1);
                int baseB = (mB >> 3) * 512 + (mB & 3) * 128 + ((mB >> 2) & 1);
                out[baseA + 2 * n]       = __uint_as_float(f2tf(v00));
                out[baseA + 2 * (n + 1)] = __uint_as_float(f2tf(v01));
                out[baseB + 2 * n]       = __uint_as_float(f2tf(v10));
                out[baseB + 2 * (n + 1)] = __uint_as_float(f2tf(v11));
            }
        }
    }
}

// ---------------------------------------------------------------------------
// Kernel 2: causal flash attention, in-block split-KV (2 groups x 4 warps).
// K smem: [key][64 permuted cols] stride 72 -> b-frag = one LDS.64,
//   conflict-free (8r+2c distinct per 16-lane phase).
// V smem: [pair_row][2*d+ph] stride 136 -> b-frag = one LDS.64,
//   conflict-free (8c+2r distinct per phase).
// Per-group smem unchanged: 4608 (K) + 4352 (V) = 8960 floats.
// ---------------------------------------------------------------------------
#define ATT_KG(g)   (sm + (g) * 8960)             // 64*72 floats
#define ATT_VG(g)   (sm + (g) * 8960 + 4608)      // 32*136 floats
#define ATT_PS      (sm + 17920)                  // + warp*1088
#define ATT_SMEM_BYTES 106496

__global__ __launch_bounds__(256, 2) void attn_kernel(float* __restrict__ out)
{
    extern __shared__ float sm[];

    const float* Q = g_QKV[0];
    const float* K = g_QKV[1];
    const float* V = g_QKV[2];

    // ---- work remap for SM pairing ----
    const int lid = blockIdx.x + 64 * blockIdx.y;   // 0..255
    int qb, b;
    if (lid < 108)        { qb = 53 - (lid >> 2);          b = lid & 3; }
    else if (lid < 148)   { int k = lid - 108; qb = 63 - (k >> 2); b = k & 3; }
    else                  { int k = lid - 148; qb = k >> 2;        b = k & 3; }

    const int t    = threadIdx.x;
    const int lane = t & 31;
    const int warp = t >> 5;
    const int g    = warp >> 2;        // split-KV group 0/1
    const int lw   = warp & 3;         // warp within group
    const int t128 = t & 127;
    const int base = b * S_LEN * HEAD;

    const int r = lane >> 2;
    const int c = lane & 3;

    float* Kb  = ATT_KG(g);
    float* Vb  = ATT_VG(g);
    float* Psw = ATT_PS + warp * 1088;

    auto pfK = [&](int kb) {
        const float* Kg = K + base + kb * 64 * HEAD;
        #pragma unroll
        for (int i = 0; i < 8; i++) {
            int idx = t128 + 128 * i;
            int row = idx >> 4, ch = idx & 15;
            cp16(Kb + row * 72 + ch * 4, Kg + row * 64 + ch * 4);
        }
    };
    auto pfV = [&](int kb) {
        const float* Vg = V + base + kb * 64 * HEAD;   // paired layout, 4096/tile
        #pragma unroll
        for (int i = 0; i < 8; i++) {
            int idx = t128 + 128 * i;
            int row = idx >> 5, ch = idx & 31;          // 32 pair-rows x 128
            cp16(Vb + row * 136 + ch * 4, Vg + row * 128 + ch * 4);
        }
    };

    // ---- Q fragments (RNA tf32, scaled) ----
    uint32_t qa[8][4];
    {
        const int qrow = qb * 64 + lw * 16 + r;
        #pragma unroll
        for (int kt = 0; kt < 8; kt++) {
            int d = kt * 8 + c;
            qa[kt][0] = f2tf(Q[base + qrow * HEAD + d] * 0.125f);
            qa[kt][1] = f2tf(Q[base + (qrow + 8) * HEAD + d] * 0.125f);
            qa[kt][2] = f2tf(Q[base + qrow * HEAD + d + 4] * 0.125f);
            qa[kt][3] = f2tf(Q[base + (qrow + 8) * HEAD + d + 4] * 0.125f);
        }
    }

    float oacc[8][4] = {};
    float mA = -1e30f, mB = -1e30f, lA = 0.0f, lB = 0.0f;

    if (g <= qb) {
        pfK(g); CP_COMMIT();
        pfV(g); CP_COMMIT();
    }

    for (int kb = g; kb <= qb; kb += 2) {
        CP_WAIT1();            // K(kb) done (V may trail)
        barg(g);

        // ---- S = Q K^T : paired K -> one LDS.64 per b-frag ----
        float sacc[8][4] = {};
        #pragma unroll
        for (int dk = 0; dk < 8; dk++) {
            #pragma unroll
            for (int nt = 0; nt < 8; nt++) {
                float2 kk = *(const float2*)(Kb + (nt * 8 + r) * 72 + dk * 8 + 2 * c);
                uint32_t bfrag[2] = { __float_as_uint(kk.x), __float_as_uint(kk.y) };
                mma_tf32(sacc[nt], qa[dk], bfrag);
            }
        }

        barg(g);               // all group warps done reading K(kb)
        if (kb + 2 <= qb) pfK(kb + 2);
        CP_COMMIT();

        // ---- causal mask on diagonal block ----
        if (kb == qb) {
            int qA = lw * 16 + r;
            int qB = qA + 8;
            #pragma unroll
            for (int nt = 0; nt < 8; nt++) {
                int k0l = nt * 8 + 2 * c;
                if (k0l     > qA) sacc[nt][0] = -1e30f;
                if (k0l + 1 > qA) sacc[nt][1] = -1e30f;
                if (k0l     > qB) sacc[nt][2] = -1e30f;
                if (k0l + 1 > qB) sacc[nt][3] = -1e30f;
            }
        }

        // ---- online softmax ----
        {
            float mxA = -1e30f, mxB = -1e30f;
            #pragma unroll
            for (int nt = 0; nt < 8; nt++) {
                mxA = fmaxf(mxA, fmaxf(sacc[nt][0], sacc[nt][1]));
                mxB = fmaxf(mxB, fmaxf(sacc[nt][2], sacc[nt][3]));
            }
            mxA = fmaxf(mxA, __shfl_xor_sync(0xffffffffu, mxA, 1, 4));
            mxA = fmaxf(mxA, __shfl_xor_sync(0xffffffffu, mxA, 2, 4));
            mxB = fmaxf(mxB, __shfl_xor_sync(0xffffffffu, mxB, 1, 4));
            mxB = fmaxf(mxB, __shfl_xor_sync(0xffffffffu, mxB, 2, 4));
            float mnA = fmaxf(mA, mxA);
            float mnB = fmaxf(mB, mxB);
            float alA = __expf(mA - mnA);
            float alB = __expf(mB - mnB);
            mA = mnA; mB = mnB;
            float rsA = 0.0f, rsB = 0.0f;
            #pragma unroll
            for (int nt = 0; nt < 8; nt++) {
                sacc[nt][0] = __expf(sacc[nt][0] - mnA);
                sacc[nt][1] = __expf(sacc[nt][1] - mnA);
                sacc[nt][2] = __expf(sacc[nt][2] - mnB);
                sacc[nt][3] = __expf(sacc[nt][3] - mnB);
                rsA += sacc[nt][0] + sacc[nt][1];
                rsB += sacc[nt][2] + sacc[nt][3];
            }
            rsA += __shfl_xor_sync(0xffffffffu, rsA, 1, 4);
            rsA += __shfl_xor_sync(0xffffffffu, rsA, 2, 4);
            rsB += __shfl_xor_sync(0xffffffffu, rsB, 1, 4);
            rsB += __shfl_xor_sync(0xffffffffu, rsB, 2, 4);
            lA = lA * alA + rsA;
            lB = lB * alB + rsB;
            #pragma unroll
            for (int dt = 0; dt < 8; dt++) {
                oacc[dt][0] *= alA; oacc[dt][1] *= alA;
                oacc[dt][2] *= alB; oacc[dt][3] *= alB;
            }
        }

        // ---- P into own warp slab (RNA tf32) ----
        #pragma unroll
        for (int nt = 0; nt < 8; nt++) {
            int col = nt * 8 + 2 * c;
            uint2 p0, p1;
            p0.x = f2tf(sacc[nt][0]); p0.y = f2tf(sacc[nt][1]);
            p1.x = f2tf(sacc[nt][2]); p1.y = f2tf(sacc[nt][3]);
            *(uint2*)&Psw[r * 68 + col]       = p0;
            *(uint2*)&Psw[(r + 8) * 68 + col] = p1;
        }
        __syncwarp();

        CP_WAIT1();            // V(kb) done (K(kb+2) may trail)
        barg(g);

        // ---- O += P V : paired V -> one LDS.64 per b-frag ----
        #pragma unroll
        for (int kt = 0; kt < 8; kt++) {
            uint32_t pa[4];
            pa[0] = __float_as_uint(Psw[r * 68 + kt * 8 + c]);
            pa[1] = __float_as_uint(Psw[(r + 8) * 68 + kt * 8 + c]);
            pa[2] = __float_as_uint(Psw[r * 68 + kt * 8 + c + 4]);
            pa[3] = __float_as_uint(Psw[(r + 8) * 68 + kt * 8 + c + 4]);
            #pragma unroll
            for (int dt = 0; dt < 8; dt++) {
                float2 vv = *(const float2*)(Vb + (kt * 4 + c) * 136 + (dt * 8 + r) * 2);
                uint32_t vbf[2] = { __float_as_uint(vv.x), __float_as_uint(vv.y) };
                mma_tf32(oacc[dt], pa, vbf);
            }
        }

        barg(g);               // all group warps done reading V(kb)
        if (kb + 2 <= qb) pfV(kb + 2);
        CP_COMMIT();
    }

    // ---- merge the two split-KV partials (scratch aliases group-0 K/V) ----
    float* MS = sm;            // 128 threads x 37 floats = 18944 B
    __syncthreads();
    if (g == 1) {
        float* p = MS + t128 * 37;
        #pragma unroll
        for (int dt = 0; dt < 8; dt++) {
            p[dt * 4 + 0] = oacc[dt][0]; p[dt * 4 + 1] = oacc[dt][1];
            p[dt * 4 + 2] = oacc[dt][2]; p[dt * 4 + 3] = oacc[dt][3];
        }
        p[32] = mA; p[33] = mB; p[34] = lA; p[35] = lB;
    }
    __syncthreads();
    if (g == 0) {
        const float* p = MS + t128 * 37;
        float m1A = p[32], m1B = p[33], l1A = p[34], l1B = p[35];
        float mnA = fmaxf(mA, m1A);
        float mnB = fmaxf(mB, m1B);
        float w0A = __expf(mA - mnA), w1A = __expf(m1A - mnA);
        float w0B = __expf(mB - mnB), w1B = __expf(m1B - mnB);
        float invA = 1.0f / (lA * w0A + l1A * w1A);
        float invB = 1.0f / (lB * w0B + l1B * w1B);
        int qrow = qb * 64 + lw * 16 + r;
        #pragma unroll
        for (int dt = 0; dt < 8; dt++) {
            float o0 = (oacc[dt][0] * w0A + p[dt * 4 + 0] * w1A) * invA;
            float o1 = (oacc[dt][1] * w0A + p[dt * 4 + 1] * w1A) * invA;
            float o2 = (oacc[dt][2] * w0B + p[dt * 4 + 2] * w1B) * invB;
            float o3 = (oacc[dt][3] * w0B + p[dt * 4 + 3] * w1B) * invB;
            int d = dt * 8 + 2 * c;
            *(float2*)&out[base + qrow * HEAD + d]       = make_float2(o0, o1);
            *(float2*)&out[base + (qrow + 8) * HEAD + d] = make_float2(o2, o3);
        }
    }
}

// ---------------------------------------------------------------------------
extern "C" void kernel_launch(void* const* d_in, const int* in_sizes, int n_in,
                              void* d_out, int out_size)
{
    const float* x  = (const float*)d_in[0];
    const float* Wq = (const float*)d_in[1];
    const float* bq = (const float*)d_in[2];
    const float* Wk = (const float*)d_in[3];
    const float* bk = (const float*)d_in[4];
    const float* Wv = (const float*)d_in[5];
    const float* bv = (const float*)d_in[6];
    float* out = (float*)d_out;

    cudaFuncSetAttribute(qkv_kernel,
        cudaFuncAttributeMaxDynamicSharedMemorySize, QKV_SMEM_BYTES);
    cudaFuncSetAttribute(attn_kernel,
        cudaFuncAttributeMaxDynamicSharedMemorySize, ATT_SMEM_BYTES);

    dim3 g1(M_TOTAL / 128, 3);
    qkv_kernel<<<g1, 256, QKV_SMEM_BYTES>>>(x, Wq, bq, Wk, bk, Wv, bv);

    dim3 g2(S_LEN / 64, BATCH);
    attn_kernel<<<g2, 256, ATT_SMEM_BYTES>>>(out);
}

// round 9
// speedup vs baseline: 5.2882x; 1.1508x over previous
#include <cuda_runtime.h>
#include <cstdint>

#define S_LEN 4096
#define EMB   1024
#define HEAD  64
#define BATCH 4
#define M_TOTAL (BATCH * S_LEN)   // 16384

__device__ float g_QKV[3][M_TOTAL * HEAD];
__device__ float g_W[3][EMB * HEAD];       // pre-rounded, b-frag-paired layout

// ---------------------------------------------------------------------------
// helpers
// ---------------------------------------------------------------------------
__device__ __forceinline__ uint32_t f2tf(float f) {
    uint32_t r;
    asm("cvt.rna.tf32.f32 %0, %1;" : "=r"(r) : "f"(f));
    return r;
}

__device__ __forceinline__ float ex2(float x) {
    float y;
    asm("ex2.approx.f32 %0, %1;" : "=f"(y) : "f"(x));
    return y;
}

__device__ __forceinline__ void mma_tf32(float c[4],
                                         const uint32_t a[4],
                                         const uint32_t b[2]) {
    asm volatile(
        "mma.sync.aligned.m16n8k8.row.col.f32.tf32.tf32.f32 "
        "{%0,%1,%2,%3}, {%4,%5,%6,%7}, {%8,%9}, {%0,%1,%2,%3};\n"
        : "+f"(c[0]), "+f"(c[1]), "+f"(c[2]), "+f"(c[3])
        : "r"(a[0]), "r"(a[1]), "r"(a[2]), "r"(a[3]),
          "r"(b[0]), "r"(b[1]));
}

__device__ __forceinline__ void cp16(float* s, const float* g) {
    uint32_t sa = (uint32_t)__cvta_generic_to_shared(s);
    asm volatile("cp.async.cg.shared.global [%0], [%1], 16;\n"
                 :: "r"(sa), "l"(g));
}
#define CP_COMMIT() asm volatile("cp.async.commit_group;\n")
#define CP_WAIT0()  asm volatile("cp.async.wait_group 0;\n")
#define CP_WAIT1()  asm volatile("cp.async.wait_group 1;\n")

__device__ __forceinline__ void barg(int g) {   // per-group named barrier
    asm volatile("bar.sync %0, 128;" :: "r"(g + 1) : "memory");
}

// ---------------------------------------------------------------------------
// Kernel 0: W prep. RNA-round W to tf32 and store in paired layout:
//   element (k, n) -> g_W[which][((k>>3)*64 + n)*8 + 2*(u&3) + (u>>2)], u=k&7
// so the b-frag pair (k = 8a+c, k = 8a+c+4) is one contiguous float2.
// ---------------------------------------------------------------------------
__global__ void wprep_kernel(const float* __restrict__ Wq,
                             const float* __restrict__ Wk,
                             const float* __restrict__ Wv)
{
    const float* src = (blockIdx.y == 0) ? Wq : (blockIdx.y == 1) ? Wk : Wv;
    int idx = blockIdx.x * 256 + threadIdx.x;    // 0 .. EMB*HEAD-1
    int k = idx >> 6, n = idx & 63;
    int u = k & 7, a = k >> 3;
    g_W[blockIdx.y][(a * 64 + n) * 8 + 2 * (u & 3) + (u >> 2)] =
        __uint_as_float(f2tf(src[idx]));
}

// ---------------------------------------------------------------------------
// Kernel 1: FUSED QKV projection. One block computes Q, K, V for 64 rows.
// BM=64, BK=32, 256 thr (8 warps: 4 m-tiles x 2 n-halves). x tile loaded once,
// A-frags built once per ks and reused across the 3 weight matrices.
// As: raw fp32 [m][k] stride 36 (4r+c bank bijection).
// Bs: paired tf32 [which*4+a][n][pair] ((8r+2c) bank bijection for LDS.64).
// Outputs: Q natural; K column-pair permuted; V row-pair interleaved.
// ---------------------------------------------------------------------------
#define QKV_AS(buf)  (sm + (buf) * 2304)          // 64*36
#define QKV_BS(buf)  (sm + 4608 + (buf) * 6144)   // 12*512
#define QKV_SMEM_BYTES 67584

__global__ __launch_bounds__(256) void qkv_kernel(const float* __restrict__ x,
    const float* __restrict__ bq, const float* __restrict__ bk,
    const float* __restrict__ bv)
{
    extern __shared__ float sm[];

    const int t    = threadIdx.x;
    const int lane = t & 31;
    const int warp = t >> 5;
    const int m0   = (warp >> 1) * 16;
    const int n0   = (warp & 1) * 32;
    const int row0 = blockIdx.x * 64;

    const int r = lane >> 2;
    const int c = lane & 3;

    auto prefetch = [&](int k0, int buf) {
        float* Ab = QKV_AS(buf);
        float* Bb = QKV_BS(buf);
        #pragma unroll
        for (int i = 0; i < 2; i++) {              // 512 cp16: x tile 64x32
            int idx = t + 256 * i;
            int m = idx >> 3, ch = idx & 7;
            cp16(Ab + m * 36 + ch * 4, x + (row0 + m) * EMB + k0 + ch * 4);
        }
        const int s = k0 >> 5;
        #pragma unroll
        for (int i = 0; i < 6; i++) {              // 1536 cp16: 3 W tiles
            int idx = t + 256 * i;
            int blk = idx >> 7;                    // which*4 + a
            int off = (idx & 127) * 4;
            cp16(Bb + blk * 512 + off,
                 g_W[blk >> 2] + ((s * 4 + (blk & 3)) * 512 + off));
        }
    };

    float acc[3][4][4] = {};

    prefetch(0, 0);
    CP_COMMIT();

    for (int step = 0; step < 32; step++) {
        const int cur = step & 1;
        CP_WAIT0();
        __syncthreads();
        if (step < 31) { prefetch((step + 1) * 32, cur ^ 1); CP_COMMIT(); }

        const float* Ab = QKV_AS(cur);
        const float* Bb = QKV_BS(cur);

        #pragma unroll
        for (int ks = 0; ks < 4; ks++) {
            const float* ap = Ab + (m0 + r) * 36 + ks * 8 + c;
            uint32_t af[4];
            af[0] = f2tf(ap[0]);
            af[1] = f2tf(ap[8 * 36]);
            af[2] = f2tf(ap[4]);
            af[3] = f2tf(ap[8 * 36 + 4]);
            #pragma unroll
            for (int w = 0; w < 3; w++) {
                #pragma unroll
                for (int nt = 0; nt < 4; nt++) {
                    float2 bb = *(const float2*)(Bb + (w * 4 + ks) * 512 +
                                                 (n0 + nt * 8 + r) * 8 + 2 * c);
                    uint32_t bf[2] = { __float_as_uint(bb.x),
                                       __float_as_uint(bb.y) };
                    mma_tf32(acc[w][nt], af, bf);
                }
            }
        }
        __syncthreads();
    }

    // ---- epilogue: +bias, per-which output layouts ----
    const int j  = 2 * c;
    const int p0 = 2 * (j & 3) + (j >> 2);
    const int p1 = 2 * ((j + 1) & 3) + ((j + 1) >> 2);
    const int mA = row0 + m0 + r;
    const int mB = mA + 8;

    #pragma unroll
    for (int w = 0; w < 3; w++) {
        const float* bias = (w == 0) ? bq : (w == 1) ? bk : bv;
        float* out = g_QKV[w];
        #pragma unroll
        for (int nt = 0; nt < 4; nt++) {
            int n = n0 + nt * 8 + 2 * c;
            float b0 = bias[n], b1 = bias[n + 1];
            float v00 = acc[w][nt][0] + b0, v01 = acc[w][nt][1] + b1;
            float v10 = acc[w][nt][2] + b0, v11 = acc[w][nt][3] + b1;

            if (w == 0) {
                *(float2*)&out[mA * HEAD + n] = make_float2(v00, v01);
                *(float2*)&out[mB * HEAD + n] = make_float2(v10, v11);
            } else if (w == 1) {
                int base8 = n0 + nt * 8;
                out[mA * HEAD + base8 + p0] = __uint_as_float(f2tf(v00));
                out[mA * HEAD + base8 + p1] = __uint_as_float(f2tf(v01));
                out[mB * HEAD + base8 + p0] = __uint_as_float(f2tf(v10));
                out[mB * HEAD + base8 + p1] = __uint_as_float(f2tf(v11));
            } else {
                int baseA = (mA >> 3) * 512 + (mA & 3) * 128 + ((mA >> 2) & 1);
                int baseB = (mB >> 3) * 512 + (mB & 3) * 128 + ((mB >> 2) & 1);
                out[baseA + 2 * n]       = __uint_as_float(f2tf(v00));
                out[baseA + 2 * (n + 1)] = __uint_as_float(f2tf(v01));
                out[baseB + 2 * n]       = __uint_as_float(f2tf(v10));
                out[baseB + 2 * (n + 1)] = __uint_as_float(f2tf(v11));
            }
        }
    }
}

// ---------------------------------------------------------------------------
// Kernel 2: causal flash attention (structure = R7; exp -> ex2 with log2e
// folded into the Q scale; all score units are log2).
// ---------------------------------------------------------------------------
#define ATT_KG(g)   (sm + (g) * 8960)
#define ATT_VG(g)   (sm + (g) * 8960 + 4608)
#define ATT_PS      (sm + 17920)
#define ATT_SMEM_BYTES 106496

#define QSCALE 0.1803368801111354f    // (1/8) * log2(e)

__global__ __launch_bounds__(256, 2) void attn_kernel(float* __restrict__ out)
{
    extern __shared__ float sm[];

    const float* Q = g_QKV[0];
    const float* K = g_QKV[1];
    const float* V = g_QKV[2];

    const int lid = blockIdx.x + 64 * blockIdx.y;
    int qb, b;
    if (lid < 108)        { qb = 53 - (lid >> 2);          b = lid & 3; }
    else if (lid < 148)   { int k = lid - 108; qb = 63 - (k >> 2); b = k & 3; }
    else                  { int k = lid - 148; qb = k >> 2;        b = k & 3; }

    const int t    = threadIdx.x;
    const int lane = t & 31;
    const int warp = t >> 5;
    const int g    = warp >> 2;
    const int lw   = warp & 3;
    const int t128 = t & 127;
    const int base = b * S_LEN * HEAD;

    const int r = lane >> 2;
    const int c = lane & 3;

    float* Kb  = ATT_KG(g);
    float* Vb  = ATT_VG(g);
    float* Psw = ATT_PS + warp * 1088;

    auto pfK = [&](int kb) {
        const float* Kg = K + base + kb * 64 * HEAD;
        #pragma unroll
        for (int i = 0; i < 8; i++) {
            int idx = t128 + 128 * i;
            int row = idx >> 4, ch = idx & 15;
            cp16(Kb + row * 72 + ch * 4, Kg + row * 64 + ch * 4);
        }
    };
    auto pfV = [&](int kb) {
        const float* Vg = V + base + kb * 64 * HEAD;
        #pragma unroll
        for (int i = 0; i < 8; i++) {
            int idx = t128 + 128 * i;
            int row = idx >> 5, ch = idx & 31;
            cp16(Vb + row * 136 + ch * 4, Vg + row * 128 + ch * 4);
        }
    };

    uint32_t qa[8][4];
    {
        const int qrow = qb * 64 + lw * 16 + r;
        #pragma unroll
        for (int kt = 0; kt < 8; kt++) {
            int d = kt * 8 + c;
            qa[kt][0] = f2tf(Q[base + qrow * HEAD + d] * QSCALE);
            qa[kt][1] = f2tf(Q[base + (qrow + 8) * HEAD + d] * QSCALE);
            qa[kt][2] = f2tf(Q[base + qrow * HEAD + d + 4] * QSCALE);
            qa[kt][3] = f2tf(Q[base + (qrow + 8) * HEAD + d + 4] * QSCALE);
        }
    }

    float oacc[8][4] = {};
    float mA = -1e30f, mB = -1e30f, lA = 0.0f, lB = 0.0f;

    if (g <= qb) {
        pfK(g); CP_COMMIT();
        pfV(g); CP_COMMIT();
    }

    for (int kb = g; kb <= qb; kb += 2) {
        CP_WAIT1();
        barg(g);

        float sacc[8][4] = {};
        #pragma unroll
        for (int dk = 0; dk < 8; dk++) {
            #pragma unroll
            for (int nt = 0; nt < 8; nt++) {
                float2 kk = *(const float2*)(Kb + (nt * 8 + r) * 72 + dk * 8 + 2 * c);
                uint32_t bfrag[2] = { __float_as_uint(kk.x), __float_as_uint(kk.y) };
                mma_tf32(sacc[nt], qa[dk], bfrag);
            }
        }

        barg(g);
        if (kb + 2 <= qb) pfK(kb + 2);
        CP_COMMIT();

        if (kb == qb) {
            int qA = lw * 16 + r;
            int qB = qA + 8;
            #pragma unroll
            for (int nt = 0; nt < 8; nt++) {
                int k0l = nt * 8 + 2 * c;
                if (k0l     > qA) sacc[nt][0] = -1e30f;
                if (k0l + 1 > qA) sacc[nt][1] = -1e30f;
                if (k0l     > qB) sacc[nt][2] = -1e30f;
                if (k0l + 1 > qB) sacc[nt][3] = -1e30f;
            }
        }

        {
            float mxA = -1e30f, mxB = -1e30f;
            #pragma unroll
            for (int nt = 0; nt < 8; nt++) {
                mxA = fmaxf(mxA, fmaxf(sacc[nt][0], sacc[nt][1]));
                mxB = fmaxf(mxB, fmaxf(sacc[nt][2], sacc[nt][3]));
            }
            mxA = fmaxf(mxA, __shfl_xor_sync(0xffffffffu, mxA, 1, 4));
            mxA = fmaxf(mxA, __shfl_xor_sync(0xffffffffu, mxA, 2, 4));
            mxB = fmaxf(mxB, __shfl_xor_sync(0xffffffffu, mxB, 1, 4));
            mxB = fmaxf(mxB, __shfl_xor_sync(0xffffffffu, mxB, 2, 4));
            float mnA = fmaxf(mA, mxA);
            float mnB = fmaxf(mB, mxB);
            float alA = ex2(mA - mnA);
            float alB = ex2(mB - mnB);
            mA = mnA; mB = mnB;
            float rsA = 0.0f, rsB = 0.0f;
            #pragma unroll
            for (int nt = 0; nt < 8; nt++) {
                sacc[nt][0] = ex2(sacc[nt][0] - mnA);
                sacc[nt][1] = ex2(sacc[nt][1] - mnA);
                sacc[nt][2] = ex2(sacc[nt][2] - mnB);
                sacc[nt][3] = ex2(sacc[nt][3] - mnB);
                rsA += sacc[nt][0] + sacc[nt][1];
                rsB += sacc[nt][2] + sacc[nt][3];
            }
            rsA += __shfl_xor_sync(0xffffffffu, rsA, 1, 4);
            rsA += __shfl_xor_sync(0xffffffffu, rsA, 2, 4);
            rsB += __shfl_xor_sync(0xffffffffu, rsB, 1, 4);
            rsB += __shfl_xor_sync(0xffffffffu, rsB, 2, 4);
            lA = lA * alA + rsA;
            lB = lB * alB + rsB;
            #pragma unroll
            for (int dt = 0; dt < 8; dt++) {
                oacc[dt][0] *= alA; oacc[dt][1] *= alA;
                oacc[dt][2] *= alB; oacc[dt][3] *= alB;
            }
        }

        #pragma unroll
        for (int nt = 0; nt < 8; nt++) {
            int col = nt * 8 + 2 * c;
            uint2 p0, p1;
            p0.x = f2tf(sacc[nt][0]); p0.y = f2tf(sacc[nt][1]);
            p1.x = f2tf(sacc[nt][2]); p1.y = f2tf(sacc[nt][3]);
            *(uint2*)&Psw[r * 68 + col]       = p0;
            *(uint2*)&Psw[(r + 8) * 68 + col] = p1;
        }
        __syncwarp();

        CP_WAIT1();
        barg(g);

        #pragma unroll
        for (int kt = 0; kt < 8; kt++) {
            uint32_t pa[4];
            pa[0] = __float_as_uint(Psw[r * 68 + kt * 8 + c]);
            pa[1] = __float_as_uint(Psw[(r + 8) * 68 + kt * 8 + c]);
            pa[2] = __float_as_uint(Psw[r * 68 + kt * 8 + c + 4]);
            pa[3] = __float_as_uint(Psw[(r + 8) * 68 + kt * 8 + c + 4]);
            #pragma unroll
            for (int dt = 0; dt < 8; dt++) {
                float2 vv = *(const float2*)(Vb + (kt * 4 + c) * 136 + (dt * 8 + r) * 2);
                uint32_t vbf[2] = { __float_as_uint(vv.x), __float_as_uint(vv.y) };
                mma_tf32(oacc[dt], pa, vbf);
            }
        }

        barg(g);
        if (kb + 2 <= qb) pfV(kb + 2);
        CP_COMMIT();
    }

    // ---- merge split-KV partials ----
    float* MS = sm;
    __syncthreads();
    if (g == 1) {
        float* p = MS + t128 * 37;
        #pragma unroll
        for (int dt = 0; dt < 8; dt++) {
            p[dt * 4 + 0] = oacc[dt][0]; p[dt * 4 + 1] = oacc[dt][1];
            p[dt * 4 + 2] = oacc[dt][2]; p[dt * 4 + 3] = oacc[dt][3];
        }
        p[32] = mA; p[33] = mB; p[34] = lA; p[35] = lB;
    }
    __syncthreads();
    if (g == 0) {
        const float* p = MS + t128 * 37;
        float m1A = p[32], m1B = p[33], l1A = p[34], l1B = p[35];
        float mnA = fmaxf(mA, m1A);
        float mnB = fmaxf(mB, m1B);
        float w0A = ex2(mA - mnA), w1A = ex2(m1A - mnA);
        float w0B = ex2(mB - mnB), w1B = ex2(m1B - mnB);
        float invA = 1.0f / (lA * w0A + l1A * w1A);
        float invB = 1.0f / (lB * w0B + l1B * w1B);
        int qrow = qb * 64 + lw * 16 + r;
        #pragma unroll
        for (int dt = 0; dt < 8; dt++) {
            float o0 = (oacc[dt][0] * w0A + p[dt * 4 + 0] * w1A) * invA;
            float o1 = (oacc[dt][1] * w0A + p[dt * 4 + 1] * w1A) * invA;
            float o2 = (oacc[dt][2] * w0B + p[dt * 4 + 2] * w1B) * invB;
            float o3 = (oacc[dt][3] * w0B + p[dt * 4 + 3] * w1B) * invB;
            int d = dt * 8 + 2 * c;
            *(float2*)&out[base + qrow * HEAD + d]       = make_float2(o0, o1);
            *(float2*)&out[base + (qrow + 8) * HEAD + d] = make_float2(o2, o3);
        }
    }
}

// ---------------------------------------------------------------------------
extern "C" void kernel_launch(void* const* d_in, const int* in_sizes, int n_in,
                              void* d_out, int out_size)
{
    const float* x  = (const float*)d_in[0];
    const float* Wq = (const float*)d_in[1];
    const float* bq = (const float*)d_in[2];
    const float* Wk = (const float*)d_in[3];
    const float* bk = (const float*)d_in[4];
    const float* Wv = (const float*)d_in[5];
    const float* bv = (const float*)d_in[6];
    float* out = (float*)d_out;

    cudaFuncSetAttribute(qkv_kernel,
        cudaFuncAttributeMaxDynamicSharedMemorySize, QKV_SMEM_BYTES);
    cudaFuncSetAttribute(attn_kernel,
        cudaFuncAttributeMaxDynamicSharedMemorySize, ATT_SMEM_BYTES);

    dim3 gw(EMB * HEAD / 256, 3);
    wprep_kernel<<<gw, 256>>>(Wq, Wk, Wv);

    qkv_kernel<<<M_TOTAL / 64, 256, QKV_SMEM_BYTES>>>(x, bq, bk, bv);

    dim3 g2(S_LEN / 64, BATCH);
    attn_kernel<<<g2, 256, ATT_SMEM_BYTES>>>(out);
}